// round 8
// baseline (speedup 1.0000x reference)
#include <cuda_runtime.h>
#include <cuda_bf16.h>
#include <math.h>
#include <float.h>

#define NB 4
#define NP 4096
#define NC 256
#define NK 16
#define NPTS (NB*NP)      /* 16384 */
#define NROWS (NPTS*NK)   /* 262144 */

// ---------------- scratch (device globals; no allocation) ----------------
__device__ float g_q [NPTS*NC];
__device__ float g_kf[NPTS*NC];
__device__ float g_vf[NPTS*NC];
__device__ int   g_idx[NROWS];
__device__ float g_u [NROWS*3];
__device__ float g_h [NROWS*NC];   // h, later reused for attn logits
__device__ float g_h2[NROWS*NC];
__device__ float g_bnd[6];         // scale[3], shift[3] for d-path BN
__device__ float g_partd[512*6];
__device__ float g_ps1[1024*NC];
__device__ float g_pq1[1024*NC];
__device__ float g_ps2[2048*NC];
__device__ float g_pq2[2048*NC];
__device__ float g_bn1[2*NC];
__device__ float g_bn2[2*NC];
// bf16 hi/lo split weights, [n][k] layout (n = output col, k = input channel)
__device__ __nv_bfloat16 g_bh1[NC*NC], g_bl1[NC*NC];
__device__ __nv_bfloat16 g_bh2[NC*NC], g_bl2[NC*NC];
__device__ __nv_bfloat16 g_bhq[NC*NC], g_blq[NC*NC];
__device__ __nv_bfloat16 g_bhk[NC*NC], g_blk[NC*NC];
__device__ __nv_bfloat16 g_bhv[NC*NC], g_blv[NC*NC];

// ---------------- exact-rounding helpers for KNN ----------------
__device__ __forceinline__ float sq3_exact(float x, float y, float z){
    return __fadd_rn(__fadd_rn(__fmul_rn(x,x), __fmul_rn(y,y)), __fmul_rn(z,z));
}
__device__ __forceinline__ float dist_exact(float qx,float qy,float qz,float qw,
                                            float px,float py,float pz,float pw){
    float dot = __fmaf_rn(qz, pz, __fmaf_rn(qy, py, __fmul_rn(qx, px)));
    return __fsub_rn(__fadd_rn(qw, pw), __fmul_rn(2.0f, dot));
}

// ---------------- KNN: one warp per query, chunked smem points ----------------
__global__ __launch_bounds__(512) void knn_kernel(const float* __restrict__ xyz)
{
    constexpr int CH = 2048;
    __shared__ float4 pts[CH];
    int b = blockIdx.y;
    const float* xb = xyz + b*NP*3;
    int warp = threadIdx.x >> 5, lane = threadIdx.x & 31;
    int n = blockIdx.x*16 + warp;
    float qx = xb[n*3+0], qy = xb[n*3+1], qz = xb[n*3+2];
    float qw = sq3_exact(qx, qy, qz);
    float dl[NK]; int il[NK];
#pragma unroll
    for (int j=0;j<NK;j++){ dl[j]=FLT_MAX; il[j]=0x7fffffff; }

    for (int c0=0;c0<NP;c0+=CH){
        __syncthreads();
        for (int i=threadIdx.x;i<CH;i+=512){
            int m=c0+i;
            float x=xb[m*3],y=xb[m*3+1],z=xb[m*3+2];
            pts[i]=make_float4(x,y,z, sq3_exact(x,y,z));
        }
        __syncthreads();
        for (int i=lane;i<CH;i+=32){
            float4 p=pts[i];
            int m=c0+i;
            float d = dist_exact(qx,qy,qz,qw, p.x,p.y,p.z,p.w);
            if (d < dl[NK-1] || (d==dl[NK-1] && m<il[NK-1])){
                dl[NK-1]=d; il[NK-1]=m;
#pragma unroll
                for (int j=NK-1;j>0;j--){
                    bool sw = dl[j]<dl[j-1] || (dl[j]==dl[j-1] && il[j]<il[j-1]);
                    float t0 = sw? dl[j-1]:dl[j];
                    float t1 = sw? dl[j]:dl[j-1];
                    int   i0 = sw? il[j-1]:il[j];
                    int   i1 = sw? il[j]:il[j-1];
                    dl[j]=t0; dl[j-1]=t1; il[j]=i0; il[j-1]=i1;
                }
            }
        }
    }
    for (int r=0;r<NK;r++){
        float cd = dl[0]; int ci = il[0];
        float rd = cd;    int ri = ci;
#pragma unroll
        for (int off=16; off>0; off>>=1){
            float od = __shfl_down_sync(0xffffffffu, rd, off);
            int   oi = __shfl_down_sync(0xffffffffu, ri, off);
            if (od<rd || (od==rd && oi<ri)){ rd=od; ri=oi; }
        }
        rd = __shfl_sync(0xffffffffu, rd, 0);
        ri = __shfl_sync(0xffffffffu, ri, 0);
        if (lane==0) g_idx[(b*NP+n)*NK + r] = ri;
        if (cd==rd && ci==ri){
#pragma unroll
            for (int j=0;j<NK-1;j++){ dl[j]=dl[j+1]; il[j]=il[j+1]; }
            dl[NK-1]=FLT_MAX; il[NK-1]=0x7fffffff;
        }
    }
}

// ---------------- d-path BN stats ----------------
__global__ __launch_bounds__(256) void dstat_kernel(const float* __restrict__ xyz,
                                                    const float* __restrict__ d1w,
                                                    const float* __restrict__ d1b)
{
    float s[3]={0.f,0.f,0.f}, sq[3]={0.f,0.f,0.f};
    int stride = gridDim.x*blockDim.x;
    for (int it = blockIdx.x*blockDim.x+threadIdx.x; it < NROWS; it += stride){
        int pt = it >> 4;
        int b  = pt >> 12;
        int j  = g_idx[it];
        float r0 = xyz[pt*3+0] - xyz[(b*NP+j)*3+0];
        float r1 = xyz[pt*3+1] - xyz[(b*NP+j)*3+1];
        float r2 = xyz[pt*3+2] - xyz[(b*NP+j)*3+2];
#pragma unroll
        for (int d=0;d<3;d++){
            float t = r0*d1w[d] + r1*d1w[3+d] + r2*d1w[6+d] + d1b[d];
            s[d]+=t; sq[d]+=t*t;
        }
    }
    __shared__ float red[256];
    for (int q=0;q<6;q++){
        red[threadIdx.x] = (q<3)? s[q] : sq[q-3];
        __syncthreads();
        for (int st=128; st; st>>=1){
            if (threadIdx.x<st) red[threadIdx.x]+=red[threadIdx.x+st];
            __syncthreads();
        }
        if (threadIdx.x==0) g_partd[blockIdx.x*6+q]=red[0];
        __syncthreads();
    }
}

__global__ void dfin_kernel(const float* __restrict__ g, const float* __restrict__ beta)
{
    int d = threadIdx.x;
    if (d>=3) return;
    double s=0.0,q=0.0;
    for (int i=0;i<512;i++){ s+=g_partd[i*6+d]; q+=g_partd[i*6+3+d]; }
    double m = s/(double)NROWS;
    double v = q/(double)NROWS - m*m;
    double sc = (double)g[d] / sqrt(v+1e-5);
    g_bnd[d]   = (float)sc;
    g_bnd[3+d] = (float)((double)beta[d] - m*sc);
}

// ---------------- weight prep (all 5 matrices, one launch) ----------------
__global__ void bprep5_kernel(const float* __restrict__ g1w, const float* __restrict__ g2w,
                              const float* __restrict__ wq,  const float* __restrict__ wk,
                              const float* __restrict__ wv)
{
    int k = blockIdx.x, n = threadIdx.x;
    const float* W; __nv_bfloat16 *H, *L;
    switch (blockIdx.y){
        case 0: W=g1w; H=g_bh1; L=g_bl1; break;
        case 1: W=g2w; H=g_bh2; L=g_bl2; break;
        case 2: W=wq;  H=g_bhq; L=g_blq; break;
        case 3: W=wk;  H=g_bhk; L=g_blk; break;
        default:W=wv;  H=g_bhv; L=g_blv; break;
    }
    float w = W[k*NC+n];
    __nv_bfloat16 h = __float2bfloat16_rn(w);
    H[n*NC+k] = h;
    L[n*NC+k] = __float2bfloat16_rn(w - __bfloat162float(h));
}

// ---------------- bf16x3 tensor-core GEMM via mma.sync (HMMA) ----------------
// C[M x 256] = f(A)[M x 256] @ W + bias; W as bf16 hi/lo [n][k].
// STATS: per-column sum/sumsq partials of C (for bn2), fused in epilogue.
__device__ __forceinline__ void mma_bf16(float* c, const unsigned* a, const unsigned* b){
    asm volatile(
      "mma.sync.aligned.m16n8k16.row.col.f32.bf16.bf16.f32 "
      "{%0,%1,%2,%3}, {%4,%5,%6,%7}, {%8,%9}, {%0,%1,%2,%3};"
      : "+f"(c[0]),"+f"(c[1]),"+f"(c[2]),"+f"(c[3])
      : "r"(a[0]),"r"(a[1]),"r"(a[2]),"r"(a[3]), "r"(b[0]),"r"(b[1]));
}

#define KC 32           /* K-chunk */
#define RSTRIDE 40      /* row stride in halves: 80B = 20 words, conflict-free */

template<bool BNRELU, bool STATS>
__global__ __launch_bounds__(256, 2) void gemm_mma_kernel(
    const float* __restrict__ A,
    const __nv_bfloat16* __restrict__ Bh, const __nv_bfloat16* __restrict__ Bl,
    const float* __restrict__ bias, const float* __restrict__ bnp,
    float* __restrict__ C, float* __restrict__ psum, float* __restrict__ psq)
{
    __shared__ __align__(16) unsigned short AsH[128][RSTRIDE];
    __shared__ __align__(16) unsigned short AsL[128][RSTRIDE];
    __shared__ __align__(16) unsigned short BsH[128][RSTRIDE];
    __shared__ __align__(16) unsigned short BsL[128][RSTRIDE];

    int tid = threadIdx.x, wid = tid >> 5, lane = tid & 31;
    int g = lane >> 2, t = lane & 3;           // fragment group / thread-in-group
    int wm = wid & 3, wn = wid >> 2;           // warp tile: 32 M-rows x 64 N-cols
    const size_t rowbase = (size_t)blockIdx.x * 128;
    const int ncb = blockIdx.y * 128;

    float acc[2][8][4];
#pragma unroll
    for (int mt=0;mt<2;mt++)
#pragma unroll
        for (int nt=0;nt<8;nt++)
#pragma unroll
            for (int i=0;i<4;i++) acc[mt][nt][i]=0.f;

    int lr = tid >> 1;            // 0..127 row for staging
    int cg = (tid & 1) * 16;      // 16-element column group

    for (int kc0 = 0; kc0 < 256; kc0 += KC){
        if (kc0) __syncthreads();
        // ---- stage A: 128 x 32 fp32 -> (bnrelu) -> hi/lo bf16 ----
        {
            const float* ap = A + (rowbase + lr)*256 + kc0 + cg;
            float v[16];
            *(float4*)(v)    = *(const float4*)(ap);
            *(float4*)(v+4)  = *(const float4*)(ap+4);
            *(float4*)(v+8)  = *(const float4*)(ap+8);
            *(float4*)(v+12) = *(const float4*)(ap+12);
            unsigned hh[8], ll[8];
#pragma unroll
            for (int p=0;p<8;p++){
                float a0 = v[p*2], a1 = v[p*2+1];
                if (BNRELU){
                    int c = kc0 + cg + p*2;
                    a0 = fmaxf(0.f, fmaf(a0, bnp[c],   bnp[256+c]));
                    a1 = fmaxf(0.f, fmaf(a1, bnp[c+1], bnp[257+c]));
                }
                __nv_bfloat16 h0 = __float2bfloat16_rn(a0);
                __nv_bfloat16 h1 = __float2bfloat16_rn(a1);
                __nv_bfloat16 l0 = __float2bfloat16_rn(a0 - __bfloat162float(h0));
                __nv_bfloat16 l1 = __float2bfloat16_rn(a1 - __bfloat162float(h1));
                hh[p] = (unsigned)__bfloat16_as_ushort(h0) | ((unsigned)__bfloat16_as_ushort(h1)<<16);
                ll[p] = (unsigned)__bfloat16_as_ushort(l0) | ((unsigned)__bfloat16_as_ushort(l1)<<16);
            }
            *(uint4*)&AsH[lr][cg]   = make_uint4(hh[0],hh[1],hh[2],hh[3]);
            *(uint4*)&AsH[lr][cg+8] = make_uint4(hh[4],hh[5],hh[6],hh[7]);
            *(uint4*)&AsL[lr][cg]   = make_uint4(ll[0],ll[1],ll[2],ll[3]);
            *(uint4*)&AsL[lr][cg+8] = make_uint4(ll[4],ll[5],ll[6],ll[7]);
        }
        // ---- stage B: 128 n-rows x 32 k bf16 hi/lo ----
        {
            const __nv_bfloat16* bhp = Bh + (size_t)(ncb + lr)*256 + kc0 + cg;
            const __nv_bfloat16* blp = Bl + (size_t)(ncb + lr)*256 + kc0 + cg;
            *(uint4*)&BsH[lr][cg]   = *(const uint4*)(bhp);
            *(uint4*)&BsH[lr][cg+8] = *(const uint4*)(bhp+8);
            *(uint4*)&BsL[lr][cg]   = *(const uint4*)(blp);
            *(uint4*)&BsL[lr][cg+8] = *(const uint4*)(blp+8);
        }
        __syncthreads();

        // ---- compute: 3 passes x 2 k16-steps x (2 m-tiles x 8 n-tiles) ----
#pragma unroll
        for (int p=0;p<3;p++){
            const unsigned short (*Ap)[RSTRIDE] = (p==2)? AsL : AsH;
            const unsigned short (*Bp)[RSTRIDE] = (p==1)? BsL : BsH;
#pragma unroll
            for (int ks=0; ks<KC; ks+=16){
                unsigned af[2][4];
#pragma unroll
                for (int mt=0;mt<2;mt++){
                    int r0 = wm*32 + mt*16 + g;
                    af[mt][0] = *(const unsigned*)&Ap[r0  ][ks + 2*t];
                    af[mt][1] = *(const unsigned*)&Ap[r0+8][ks + 2*t];
                    af[mt][2] = *(const unsigned*)&Ap[r0  ][ks + 2*t + 8];
                    af[mt][3] = *(const unsigned*)&Ap[r0+8][ks + 2*t + 8];
                }
#pragma unroll
                for (int nt=0;nt<8;nt++){
                    int n0 = wn*64 + nt*8 + g;
                    unsigned bf[2];
                    bf[0] = *(const unsigned*)&Bp[n0][ks + 2*t];
                    bf[1] = *(const unsigned*)&Bp[n0][ks + 2*t + 8];
                    mma_bf16(acc[0][nt], af[0], bf);
                    mma_bf16(acc[1][nt], af[1], bf);
                }
            }
        }
    }

    // ---- epilogue: bias into acc, store, optional fused column stats ----
#pragma unroll
    for (int nt=0;nt<8;nt++){
        int col = ncb + wn*64 + nt*8 + 2*t;
        float b0 = bias[col], b1 = bias[col+1];
#pragma unroll
        for (int mt=0;mt<2;mt++){
            acc[mt][nt][0]+=b0; acc[mt][nt][1]+=b1;
            acc[mt][nt][2]+=b0; acc[mt][nt][3]+=b1;
        }
    }
#pragma unroll
    for (int nt=0;nt<8;nt++){
        int col = ncb + wn*64 + nt*8 + 2*t;
#pragma unroll
        for (int mt=0;mt<2;mt++){
            size_t row = rowbase + wm*32 + mt*16 + g;
            *(float2*)&C[row*256 + col]     = make_float2(acc[mt][nt][0], acc[mt][nt][1]);
            *(float2*)&C[(row+8)*256 + col] = make_float2(acc[mt][nt][2], acc[mt][nt][3]);
        }
    }

    if (STATS){
        __syncthreads();                      // safe to reuse AsH as scratch now
        float* sS = (float*)AsH;              // [4][128]
        float* sQ = sS + 512;                 // [4][128]
#pragma unroll
        for (int nt=0;nt<8;nt++){
            float s0=0.f,q0=0.f,s1=0.f,q1=0.f;
#pragma unroll
            for (int mt=0;mt<2;mt++){
                float v0=acc[mt][nt][0], v2=acc[mt][nt][2];
                float v1=acc[mt][nt][1], v3=acc[mt][nt][3];
                s0 += v0+v2;  q0 += v0*v0+v2*v2;
                s1 += v1+v3;  q1 += v1*v1+v3*v3;
            }
#pragma unroll
            for (int off=16; off>=4; off>>=1){
                s0 += __shfl_down_sync(0xffffffffu, s0, off);
                q0 += __shfl_down_sync(0xffffffffu, q0, off);
                s1 += __shfl_down_sync(0xffffffffu, s1, off);
                q1 += __shfl_down_sync(0xffffffffu, q1, off);
            }
            if (lane < 4){
                int c = wn*64 + nt*8 + 2*lane;
                sS[wm*128 + c]     = s0;  sS[wm*128 + c + 1] = s1;
                sQ[wm*128 + c]     = q0;  sQ[wm*128 + c + 1] = q1;
            }
        }
        __syncthreads();
        if (tid < 128){
            float s = sS[tid] + sS[128+tid] + sS[256+tid] + sS[384+tid];
            float q = sQ[tid] + sQ[128+tid] + sQ[256+tid] + sQ[384+tid];
            psum[blockIdx.x*256 + ncb + tid] = s;
            psq [blockIdx.x*256 + ncb + tid] = q;
        }
    }
}

// ---------------- finalize per-channel BN over 256 channels ----------------
__global__ __launch_bounds__(256) void bnfin_kernel(const float* __restrict__ psum,
                                                    const float* __restrict__ psq, int P,
                                                    const float* __restrict__ g,
                                                    const float* __restrict__ beta,
                                                    float* __restrict__ outp)
{
    int c = threadIdx.x;
    double s=0.0,q=0.0;
    for (int i=0;i<P;i++){ s+=psum[i*NC+c]; q+=psq[i*NC+c]; }
    double m = s/(double)NROWS;
    double v = q/(double)NROWS - m*m;
    double sc = (double)g[c] / sqrt(v+1e-5);
    outp[c]    = (float)sc;
    outp[NC+c] = (float)((double)beta[c] - m*sc);
}

// ---------------- h producer: h = q - k[idx] + pos_enc; fused bn1 stats ----------------
__global__ __launch_bounds__(256) void hprod_kernel(
    const float* __restrict__ xyz, const float* __restrict__ d1w, const float* __restrict__ d1b,
    const float* __restrict__ d2w, const float* __restrict__ d2b)
{
    __shared__ float su[NK*3];
    __shared__ int   sj[NK];
    int c = threadIdx.x;
    float d2c0 = d2w[c], d2c1 = d2w[256+c], d2c2 = d2w[512+c], d2bc = d2b[c];
    float s=0.f, q=0.f;
    for (int pp=0; pp<16; pp++){
        int pt = blockIdx.x*16 + pp;
        int b  = pt >> 12;
        if (c < NK){
            int k = c;
            int j = g_idx[pt*NK+k];
            sj[k]=j;
            float r0 = xyz[pt*3+0]-xyz[(b*NP+j)*3+0];
            float r1 = xyz[pt*3+1]-xyz[(b*NP+j)*3+1];
            float r2 = xyz[pt*3+2]-xyz[(b*NP+j)*3+2];
#pragma unroll
            for (int d=0;d<3;d++){
                float t  = r0*d1w[d] + r1*d1w[3+d] + r2*d1w[6+d] + d1b[d];
                float uu = fmaxf(0.f, fmaf(t, g_bnd[d], g_bnd[3+d]));
                su[k*3+d]=uu;
                g_u[(pt*NK+k)*3+d]=uu;
            }
        }
        __syncthreads();
        float qv = g_q[pt*NC + c];
#pragma unroll
        for (int k=0;k<NK;k++){
            int j = sj[k];
            float kv = g_kf[(b*NP+j)*NC + c];
            float pe = su[k*3]*d2c0 + su[k*3+1]*d2c1 + su[k*3+2]*d2c2 + d2bc;
            float h = qv - kv + pe;
            g_h[(size_t)(pt*NK+k)*NC + c] = h;
            s += h; q += h*h;
        }
        __syncthreads();
    }
    g_ps1[blockIdx.x*NC+c]=s;
    g_pq1[blockIdx.x*NC+c]=q;
}

// ---------------- softmax over K + weighted gather output ----------------
__global__ __launch_bounds__(256) void out_kernel(
    float* __restrict__ out, const float* __restrict__ d2w, const float* __restrict__ d2b)
{
    __shared__ float su[NK*3];
    __shared__ int   sj[NK];
    int pt = blockIdx.x;
    int b  = pt >> 12;
    int a  = threadIdx.x;
    if (a < NK)   sj[a] = g_idx[pt*NK+a];
    if (a < NK*3) su[a] = g_u[pt*NK*3 + a];
    __syncthreads();
    float d0=d2w[a], d1=d2w[256+a], d2=d2w[512+a], db=d2b[a];
    float e[NK];
    float mx = -FLT_MAX;
#pragma unroll
    for (int k=0;k<NK;k++){
        float x = g_h[(size_t)(pt*NK+k)*NC + a];
        e[k]=x; mx = fmaxf(mx,x);
    }
    float sm=0.f;
#pragma unroll
    for (int k=0;k<NK;k++){ e[k]=expf(e[k]-mx); sm+=e[k]; }
    float inv = 1.f/sm;
    float o=0.f;
#pragma unroll
    for (int k=0;k<NK;k++){
        int j = sj[k];
        float v  = g_vf[(b*NP+j)*NC + a];
        float pe = su[k*3]*d0 + su[k*3+1]*d1 + su[k*3+2]*d2 + db;
        o += e[k]*inv*(v+pe);
    }
    out[pt*NC + a] = o;
}

// ---------------- host launcher (graph-capturable, allocation-free) ----------------
extern "C" void kernel_launch(void* const* d_in, const int* in_sizes, int n_in,
                              void* d_out, int out_size)
{
    const float* xyz  = (const float*)d_in[0];
    const float* feat = (const float*)d_in[1];
    const float* wq   = (const float*)d_in[2];  const float* bq  = (const float*)d_in[3];
    const float* wk   = (const float*)d_in[4];  const float* bk  = (const float*)d_in[5];
    const float* wv   = (const float*)d_in[6];  const float* bv  = (const float*)d_in[7];
    const float* d1w  = (const float*)d_in[8];  const float* d1b = (const float*)d_in[9];
    const float* bndg = (const float*)d_in[10]; const float* bndb= (const float*)d_in[11];
    const float* d2w  = (const float*)d_in[12]; const float* d2b = (const float*)d_in[13];
    const float* g1g  = (const float*)d_in[14]; const float* g1bt= (const float*)d_in[15];
    const float* g1w  = (const float*)d_in[16]; const float* g1b = (const float*)d_in[17];
    const float* g2g  = (const float*)d_in[18]; const float* g2bt= (const float*)d_in[19];
    const float* g2w  = (const float*)d_in[20]; const float* g2b = (const float*)d_in[21];
    float* out = (float*)d_out;

    float *p_q,*p_kf,*p_vf,*p_h,*p_h2,*p_bn1,*p_bn2,*p_ps1,*p_pq1,*p_ps2,*p_pq2;
    __nv_bfloat16 *p_bh1,*p_bl1,*p_bh2,*p_bl2,*p_bhq,*p_blq,*p_bhk,*p_blk,*p_bhv,*p_blv;
    cudaGetSymbolAddress((void**)&p_q,  g_q);
    cudaGetSymbolAddress((void**)&p_kf, g_kf);
    cudaGetSymbolAddress((void**)&p_vf, g_vf);
    cudaGetSymbolAddress((void**)&p_h,  g_h);
    cudaGetSymbolAddress((void**)&p_h2, g_h2);
    cudaGetSymbolAddress((void**)&p_bn1,g_bn1);
    cudaGetSymbolAddress((void**)&p_bn2,g_bn2);
    cudaGetSymbolAddress((void**)&p_ps1,g_ps1);
    cudaGetSymbolAddress((void**)&p_pq1,g_pq1);
    cudaGetSymbolAddress((void**)&p_ps2,g_ps2);
    cudaGetSymbolAddress((void**)&p_pq2,g_pq2);
    cudaGetSymbolAddress((void**)&p_bh1,g_bh1);
    cudaGetSymbolAddress((void**)&p_bl1,g_bl1);
    cudaGetSymbolAddress((void**)&p_bh2,g_bh2);
    cudaGetSymbolAddress((void**)&p_bl2,g_bl2);
    cudaGetSymbolAddress((void**)&p_bhq,g_bhq);
    cudaGetSymbolAddress((void**)&p_blq,g_blq);
    cudaGetSymbolAddress((void**)&p_bhk,g_bhk);
    cudaGetSymbolAddress((void**)&p_blk,g_blk);
    cudaGetSymbolAddress((void**)&p_bhv,g_bhv);
    cudaGetSymbolAddress((void**)&p_blv,g_blv);

    // 1. KNN indices
    knn_kernel<<<dim3(NP/16, NB), 512>>>(xyz);
    // 2. d-path BN stats + finalize; all weight splits in ONE launch
    dstat_kernel<<<512,256>>>(xyz, d1w, d1b);
    dfin_kernel<<<1,32>>>(bndg, bndb);
    bprep5_kernel<<<dim3(NC,5),NC>>>(g1w, g2w, wq, wk, wv);
    // 3. q / k / v projections (HMMA bf16x3) — launch #6 is gemmk for ncu
    gemm_mma_kernel<false,false><<<dim3(NPTS/128,2),256>>>(feat, p_bhq, p_blq, bq, nullptr, p_q,  nullptr, nullptr);
    gemm_mma_kernel<false,false><<<dim3(NPTS/128,2),256>>>(feat, p_bhk, p_blk, bk, nullptr, p_kf, nullptr, nullptr);
    gemm_mma_kernel<false,false><<<dim3(NPTS/128,2),256>>>(feat, p_bhv, p_blv, bv, nullptr, p_vf, nullptr, nullptr);
    // 4. h = q - k[idx] + pos_enc (stores u, fused bn1 stats)
    hprod_kernel<<<1024,256>>>(xyz, d1w, d1b, d2w, d2b);
    bnfin_kernel<<<1,256>>>(p_ps1, p_pq1, 1024, g1g, g1bt, p_bn1);
    // 5. gamma layer 1 (HMMA): relu(bn1(h)) @ g1_w + g1_b -> h2, fused bn2 stats
    gemm_mma_kernel<true,true><<<dim3(NROWS/128,2),256>>>(p_h, p_bh1, p_bl1, g1b, p_bn1, p_h2, p_ps2, p_pq2);
    bnfin_kernel<<<1,256>>>(p_ps2, p_pq2, 2048, g2g, g2bt, p_bn2);
    // 6. gamma layer 2 (HMMA): relu(bn2(h2)) @ g2_w + g2_b -> attn logits
    gemm_mma_kernel<true,false><<<dim3(NROWS/128,2),256>>>(p_h2, p_bh2, p_bl2, g2b, p_bn2, p_h, nullptr, nullptr);
    // 7. softmax over K + weighted (v + pos_enc) sum
    out_kernel<<<NPTS,256>>>(out, d2w, d2b);
}

// round 10
// speedup vs baseline: 1.0205x; 1.0205x over previous
#include <cuda_runtime.h>
#include <cuda_bf16.h>
#include <math.h>
#include <float.h>

#define NB 4
#define NP 4096
#define NC 256
#define NK 16
#define NPTS (NB*NP)      /* 16384 */
#define NROWS (NPTS*NK)   /* 262144 */

// ---------------- scratch (device globals; no allocation) ----------------
__device__ float g_q [NPTS*NC];
__device__ float g_kf[NPTS*NC];
__device__ float g_vf[NPTS*NC];
__device__ int   g_idx[NROWS];
__device__ float g_u [NROWS*3];
__device__ float g_h [NROWS*NC];
__device__ float g_h2[NROWS*NC];
__device__ float g_bnd[6];         // scale[3], shift[3] for d-path BN
__device__ float g_partd[512*6];
__device__ float g_ps1[512*NC];
__device__ float g_pq1[512*NC];
__device__ float g_ps2[2048*NC];
__device__ float g_pq2[2048*NC];
__device__ float g_bn1[2*NC];
__device__ float g_bn2[2*NC];
// bf16 hi/lo split weights, [n][k] layout (n = output col, k = input channel)
__device__ __nv_bfloat16 g_bh1[NC*NC], g_bl1[NC*NC];
__device__ __nv_bfloat16 g_bh2[NC*NC], g_bl2[NC*NC];
__device__ __nv_bfloat16 g_bhq[NC*NC], g_blq[NC*NC];
__device__ __nv_bfloat16 g_bhk[NC*NC], g_blk[NC*NC];
__device__ __nv_bfloat16 g_bhv[NC*NC], g_blv[NC*NC];

// ---------------- exact-rounding helpers for KNN ----------------
__device__ __forceinline__ float sq3_exact(float x, float y, float z){
    return __fadd_rn(__fadd_rn(__fmul_rn(x,x), __fmul_rn(y,y)), __fmul_rn(z,z));
}
__device__ __forceinline__ float dist_exact(float qx,float qy,float qz,float qw,
                                            float px,float py,float pz,float pw){
    float dot = __fmaf_rn(qz, pz, __fmaf_rn(qy, py, __fmul_rn(qx, px)));
    return __fsub_rn(__fadd_rn(qw, pw), __fmul_rn(2.0f, dot));
}

// ---------------- KNN: one warp per query, chunked smem points ----------------
__global__ __launch_bounds__(512) void knn_kernel(const float* __restrict__ xyz)
{
    constexpr int CH = 2048;
    __shared__ float4 pts[CH];
    int b = blockIdx.y;
    const float* xb = xyz + b*NP*3;
    int warp = threadIdx.x >> 5, lane = threadIdx.x & 31;
    int n = blockIdx.x*16 + warp;
    float qx = xb[n*3+0], qy = xb[n*3+1], qz = xb[n*3+2];
    float qw = sq3_exact(qx, qy, qz);
    float dl[NK]; int il[NK];
#pragma unroll
    for (int j=0;j<NK;j++){ dl[j]=FLT_MAX; il[j]=0x7fffffff; }

    for (int c0=0;c0<NP;c0+=CH){
        __syncthreads();
        for (int i=threadIdx.x;i<CH;i+=512){
            int m=c0+i;
            float x=xb[m*3],y=xb[m*3+1],z=xb[m*3+2];
            pts[i]=make_float4(x,y,z, sq3_exact(x,y,z));
        }
        __syncthreads();
        for (int i=lane;i<CH;i+=32){
            float4 p=pts[i];
            int m=c0+i;
            float d = dist_exact(qx,qy,qz,qw, p.x,p.y,p.z,p.w);
            if (d < dl[NK-1] || (d==dl[NK-1] && m<il[NK-1])){
                dl[NK-1]=d; il[NK-1]=m;
#pragma unroll
                for (int j=NK-1;j>0;j--){
                    bool sw = dl[j]<dl[j-1] || (dl[j]==dl[j-1] && il[j]<il[j-1]);
                    float t0 = sw? dl[j-1]:dl[j];
                    float t1 = sw? dl[j]:dl[j-1];
                    int   i0 = sw? il[j-1]:il[j];
                    int   i1 = sw? il[j]:il[j-1];
                    dl[j]=t0; dl[j-1]=t1; il[j]=i0; il[j-1]=i1;
                }
            }
        }
    }
    for (int r=0;r<NK;r++){
        float cd = dl[0]; int ci = il[0];
        float rd = cd;    int ri = ci;
#pragma unroll
        for (int off=16; off>0; off>>=1){
            float od = __shfl_down_sync(0xffffffffu, rd, off);
            int   oi = __shfl_down_sync(0xffffffffu, ri, off);
            if (od<rd || (od==rd && oi<ri)){ rd=od; ri=oi; }
        }
        rd = __shfl_sync(0xffffffffu, rd, 0);
        ri = __shfl_sync(0xffffffffu, ri, 0);
        if (lane==0) g_idx[(b*NP+n)*NK + r] = ri;
        if (cd==rd && ci==ri){
#pragma unroll
            for (int j=0;j<NK-1;j++){ dl[j]=dl[j+1]; il[j]=il[j+1]; }
            dl[NK-1]=FLT_MAX; il[NK-1]=0x7fffffff;
        }
    }
}

// ---------------- d-path BN stats ----------------
__global__ __launch_bounds__(256) void dstat_kernel(const float* __restrict__ xyz,
                                                    const float* __restrict__ d1w,
                                                    const float* __restrict__ d1b)
{
    float s[3]={0.f,0.f,0.f}, sq[3]={0.f,0.f,0.f};
    int stride = gridDim.x*blockDim.x;
    for (int it = blockIdx.x*blockDim.x+threadIdx.x; it < NROWS; it += stride){
        int pt = it >> 4;
        int b  = pt >> 12;
        int j  = g_idx[it];
        float r0 = xyz[pt*3+0] - xyz[(b*NP+j)*3+0];
        float r1 = xyz[pt*3+1] - xyz[(b*NP+j)*3+1];
        float r2 = xyz[pt*3+2] - xyz[(b*NP+j)*3+2];
#pragma unroll
        for (int d=0;d<3;d++){
            float t = r0*d1w[d] + r1*d1w[3+d] + r2*d1w[6+d] + d1b[d];
            s[d]+=t; sq[d]+=t*t;
        }
    }
    __shared__ float red[256];
    for (int q=0;q<6;q++){
        red[threadIdx.x] = (q<3)? s[q] : sq[q-3];
        __syncthreads();
        for (int st=128; st; st>>=1){
            if (threadIdx.x<st) red[threadIdx.x]+=red[threadIdx.x+st];
            __syncthreads();
        }
        if (threadIdx.x==0) g_partd[blockIdx.x*6+q]=red[0];
        __syncthreads();
    }
}

__global__ void dfin_kernel(const float* __restrict__ g, const float* __restrict__ beta)
{
    int d = threadIdx.x;
    if (d>=3) return;
    double s=0.0,q=0.0;
    for (int i=0;i<512;i++){ s+=g_partd[i*6+d]; q+=g_partd[i*6+3+d]; }
    double m = s/(double)NROWS;
    double v = q/(double)NROWS - m*m;
    double sc = (double)g[d] / sqrt(v+1e-5);
    g_bnd[d]   = (float)sc;
    g_bnd[3+d] = (float)((double)beta[d] - m*sc);
}

// ---------------- weight prep (all 5 matrices, one launch) ----------------
__global__ void bprep5_kernel(const float* __restrict__ g1w, const float* __restrict__ g2w,
                              const float* __restrict__ wq,  const float* __restrict__ wk,
                              const float* __restrict__ wv)
{
    int k = blockIdx.x, n = threadIdx.x;
    const float* W; __nv_bfloat16 *H, *L;
    switch (blockIdx.y){
        case 0: W=g1w; H=g_bh1; L=g_bl1; break;
        case 1: W=g2w; H=g_bh2; L=g_bl2; break;
        case 2: W=wq;  H=g_bhq; L=g_blq; break;
        case 3: W=wk;  H=g_bhk; L=g_blk; break;
        default:W=wv;  H=g_bhv; L=g_blv; break;
    }
    float w = W[k*NC+n];
    __nv_bfloat16 h = __float2bfloat16_rn(w);
    H[n*NC+k] = h;
    L[n*NC+k] = __float2bfloat16_rn(w - __bfloat162float(h));
}

// ---------------- HMMA helpers ----------------
__device__ __forceinline__ void mma_bf16(float* c, const unsigned* a, const unsigned* b){
    asm volatile(
      "mma.sync.aligned.m16n8k16.row.col.f32.bf16.bf16.f32 "
      "{%0,%1,%2,%3}, {%4,%5,%6,%7}, {%8,%9}, {%0,%1,%2,%3};"
      : "+f"(c[0]),"+f"(c[1]),"+f"(c[2]),"+f"(c[3])
      : "r"(a[0]),"r"(a[1]),"r"(a[2]),"r"(a[3]), "r"(b[0]),"r"(b[1]));
}

#define KC 32           /* K-chunk */
#define RSTRIDE 40      /* row stride in halves: 80B = 20 words, conflict-free */
#define TILE_BYTES (128*RSTRIDE*2)

// Shared mainloop: stages f(A) (bf16 hi/lo) and W (hi/lo) tiles, runs 3 HMMA passes.
template<bool BNRELU>
__device__ __forceinline__ void gemm_mainloop(
    const float* __restrict__ A, const __nv_bfloat16* __restrict__ Bh,
    const __nv_bfloat16* __restrict__ Bl, const float* __restrict__ bnp,
    unsigned short (*AsH)[RSTRIDE], unsigned short (*AsL)[RSTRIDE],
    unsigned short (*BsH)[RSTRIDE], unsigned short (*BsL)[RSTRIDE],
    size_t rowbase, int ncb, int tid, int g, int t, int wm, int wn,
    float acc[2][8][4])
{
    int lr = tid >> 1;
    int cg = (tid & 1) * 16;
    for (int kc0 = 0; kc0 < 256; kc0 += KC){
        if (kc0) __syncthreads();
        {
            const float* ap = A + (rowbase + lr)*256 + kc0 + cg;
            float v[16];
            *(float4*)(v)    = *(const float4*)(ap);
            *(float4*)(v+4)  = *(const float4*)(ap+4);
            *(float4*)(v+8)  = *(const float4*)(ap+8);
            *(float4*)(v+12) = *(const float4*)(ap+12);
            unsigned hh[8], ll[8];
#pragma unroll
            for (int p=0;p<8;p++){
                float a0 = v[p*2], a1 = v[p*2+1];
                if (BNRELU){
                    int c = kc0 + cg + p*2;
                    a0 = fmaxf(0.f, fmaf(a0, bnp[c],   bnp[256+c]));
                    a1 = fmaxf(0.f, fmaf(a1, bnp[c+1], bnp[257+c]));
                }
                __nv_bfloat16 h0 = __float2bfloat16_rn(a0);
                __nv_bfloat16 h1 = __float2bfloat16_rn(a1);
                __nv_bfloat16 l0 = __float2bfloat16_rn(a0 - __bfloat162float(h0));
                __nv_bfloat16 l1 = __float2bfloat16_rn(a1 - __bfloat162float(h1));
                hh[p] = (unsigned)__bfloat16_as_ushort(h0) | ((unsigned)__bfloat16_as_ushort(h1)<<16);
                ll[p] = (unsigned)__bfloat16_as_ushort(l0) | ((unsigned)__bfloat16_as_ushort(l1)<<16);
            }
            *(uint4*)&AsH[lr][cg]   = make_uint4(hh[0],hh[1],hh[2],hh[3]);
            *(uint4*)&AsH[lr][cg+8] = make_uint4(hh[4],hh[5],hh[6],hh[7]);
            *(uint4*)&AsL[lr][cg]   = make_uint4(ll[0],ll[1],ll[2],ll[3]);
            *(uint4*)&AsL[lr][cg+8] = make_uint4(ll[4],ll[5],ll[6],ll[7]);
        }
        {
            const __nv_bfloat16* bhp = Bh + (size_t)(ncb + lr)*256 + kc0 + cg;
            const __nv_bfloat16* blp = Bl + (size_t)(ncb + lr)*256 + kc0 + cg;
            *(uint4*)&BsH[lr][cg]   = *(const uint4*)(bhp);
            *(uint4*)&BsH[lr][cg+8] = *(const uint4*)(bhp+8);
            *(uint4*)&BsL[lr][cg]   = *(const uint4*)(blp);
            *(uint4*)&BsL[lr][cg+8] = *(const uint4*)(blp+8);
        }
        __syncthreads();
#pragma unroll
        for (int p=0;p<3;p++){
            const unsigned short (*Ap)[RSTRIDE] = (p==2)? AsL : AsH;
            const unsigned short (*Bp)[RSTRIDE] = (p==1)? BsL : BsH;
#pragma unroll
            for (int ks=0; ks<KC; ks+=16){
                unsigned af[2][4];
#pragma unroll
                for (int mt=0;mt<2;mt++){
                    int r0 = wm*32 + mt*16 + g;
                    af[mt][0] = *(const unsigned*)&Ap[r0  ][ks + 2*t];
                    af[mt][1] = *(const unsigned*)&Ap[r0+8][ks + 2*t];
                    af[mt][2] = *(const unsigned*)&Ap[r0  ][ks + 2*t + 8];
                    af[mt][3] = *(const unsigned*)&Ap[r0+8][ks + 2*t + 8];
                }
#pragma unroll
                for (int nt=0;nt<8;nt++){
                    int n0 = wn*64 + nt*8 + g;
                    unsigned bf[2];
                    bf[0] = *(const unsigned*)&Bp[n0][ks + 2*t];
                    bf[1] = *(const unsigned*)&Bp[n0][ks + 2*t + 8];
                    mma_bf16(acc[0][nt], af[0], bf);
                    mma_bf16(acc[1][nt], af[1], bf);
                }
            }
        }
    }
}

// ---------------- GEMM (qkv / gamma1): store C, optional BN+fused stats ----------------
template<bool BNRELU, bool STATS>
__global__ __launch_bounds__(256, 2) void gemm_mma_kernel(
    const float* __restrict__ A,
    const __nv_bfloat16* __restrict__ Bh, const __nv_bfloat16* __restrict__ Bl,
    const float* __restrict__ bias, const float* __restrict__ bnp,
    float* __restrict__ C, float* __restrict__ psum, float* __restrict__ psq)
{
    __shared__ __align__(16) unsigned short AsH[128][RSTRIDE];
    __shared__ __align__(16) unsigned short AsL[128][RSTRIDE];
    __shared__ __align__(16) unsigned short BsH[128][RSTRIDE];
    __shared__ __align__(16) unsigned short BsL[128][RSTRIDE];

    int tid = threadIdx.x, wid = tid >> 5, lane = tid & 31;
    int g = lane >> 2, t = lane & 3;
    int wm = wid & 3, wn = wid >> 2;
    const size_t rowbase = (size_t)blockIdx.x * 128;
    const int ncb = blockIdx.y * 128;

    float acc[2][8][4];
#pragma unroll
    for (int mt=0;mt<2;mt++)
#pragma unroll
        for (int nt=0;nt<8;nt++)
#pragma unroll
            for (int i=0;i<4;i++) acc[mt][nt][i]=0.f;

    gemm_mainloop<BNRELU>(A, Bh, Bl, bnp, AsH, AsL, BsH, BsL,
                          rowbase, ncb, tid, g, t, wm, wn, acc);

#pragma unroll
    for (int nt=0;nt<8;nt++){
        int col = ncb + wn*64 + nt*8 + 2*t;
        float b0 = bias[col], b1 = bias[col+1];
#pragma unroll
        for (int mt=0;mt<2;mt++){
            acc[mt][nt][0]+=b0; acc[mt][nt][1]+=b1;
            acc[mt][nt][2]+=b0; acc[mt][nt][3]+=b1;
        }
    }
#pragma unroll
    for (int nt=0;nt<8;nt++){
        int col = ncb + wn*64 + nt*8 + 2*t;
#pragma unroll
        for (int mt=0;mt<2;mt++){
            size_t row = rowbase + wm*32 + mt*16 + g;
            *(float2*)&C[row*256 + col]     = make_float2(acc[mt][nt][0], acc[mt][nt][1]);
            *(float2*)&C[(row+8)*256 + col] = make_float2(acc[mt][nt][2], acc[mt][nt][3]);
        }
    }

    if (STATS){
        __syncthreads();
        float* sS = (float*)AsH;              // [4][128]
        float* sQ = sS + 512;
#pragma unroll
        for (int nt=0;nt<8;nt++){
            float s0=0.f,q0=0.f,s1=0.f,q1=0.f;
#pragma unroll
            for (int mt=0;mt<2;mt++){
                float v0=acc[mt][nt][0], v2=acc[mt][nt][2];
                float v1=acc[mt][nt][1], v3=acc[mt][nt][3];
                s0 += v0+v2;  q0 += v0*v0+v2*v2;
                s1 += v1+v3;  q1 += v1*v1+v3*v3;
            }
#pragma unroll
            for (int off=16; off>=4; off>>=1){
                s0 += __shfl_down_sync(0xffffffffu, s0, off);
                q0 += __shfl_down_sync(0xffffffffu, q0, off);
                s1 += __shfl_down_sync(0xffffffffu, s1, off);
                q1 += __shfl_down_sync(0xffffffffu, q1, off);
            }
            if (lane < 4){
                int c = wn*64 + nt*8 + 2*lane;
                sS[wm*128 + c]     = s0;  sS[wm*128 + c + 1] = s1;
                sQ[wm*128 + c]     = q0;  sQ[wm*128 + c + 1] = q1;
            }
        }
        __syncthreads();
        if (tid < 128){
            float s = sS[tid] + sS[128+tid] + sS[256+tid] + sS[384+tid];
            float q = sQ[tid] + sQ[128+tid] + sQ[256+tid] + sQ[384+tid];
            psum[blockIdx.x*256 + ncb + tid] = s;
            psq [blockIdx.x*256 + ncb + tid] = q;
        }
    }
}

// ---------------- fused gamma2 + softmax(K) + weighted output ----------------
// CTA = 8 points x 16 neighbors (128 rows) x 128 cols. Logits stay in registers;
// softmax over K via shfl_xor over g-groups; v gathered into (reused) smem.
// VSTRIDE must be a multiple of 4 so r*VSTRIDE float4 stores stay 16B-aligned.
#define VSTRIDE 132
__global__ __launch_bounds__(256, 2) void gemm_attn_kernel(
    const float* __restrict__ A,
    const __nv_bfloat16* __restrict__ Bh, const __nv_bfloat16* __restrict__ Bl,
    const float* __restrict__ bias, const float* __restrict__ bnp,
    const float* __restrict__ d2w, const float* __restrict__ d2b,
    float* __restrict__ out)
{
    extern __shared__ __align__(16) char dsm[];
    unsigned short (*AsH)[RSTRIDE] = (unsigned short(*)[RSTRIDE])(dsm);
    unsigned short (*AsL)[RSTRIDE] = (unsigned short(*)[RSTRIDE])(dsm + TILE_BYTES);
    unsigned short (*BsH)[RSTRIDE] = (unsigned short(*)[RSTRIDE])(dsm + 2*TILE_BYTES);
    unsigned short (*BsL)[RSTRIDE] = (unsigned short(*)[RSTRIDE])(dsm + 3*TILE_BYTES);
    float* Vs = (float*)dsm;                     // reused after mainloop: 128 x VSTRIDE

    int tid = threadIdx.x, wid = tid >> 5, lane = tid & 31;
    int g = lane >> 2, t = lane & 3;
    int wm = wid & 3, wn = wid >> 2;
    const size_t rowbase = (size_t)blockIdx.x * 128;
    const int ncb = blockIdx.y * 128;

    float acc[2][8][4];
#pragma unroll
    for (int mt=0;mt<2;mt++)
#pragma unroll
        for (int nt=0;nt<8;nt++)
#pragma unroll
            for (int i=0;i<4;i++) acc[mt][nt][i]=0.f;

    gemm_mainloop<true>(A, Bh, Bl, bnp, AsH, AsL, BsH, BsL,
                        rowbase, ncb, tid, g, t, wm, wn, acc);

    // bias -> logits
#pragma unroll
    for (int nt=0;nt<8;nt++){
        int col = ncb + wn*64 + nt*8 + 2*t;
        float b0 = bias[col], b1 = bias[col+1];
#pragma unroll
        for (int mt=0;mt<2;mt++){
            acc[mt][nt][0]+=b0; acc[mt][nt][1]+=b1;
            acc[mt][nt][2]+=b0; acc[mt][nt][3]+=b1;
        }
    }

    __syncthreads();   // tiles no longer needed; reuse as Vs

    // stage gathered v rows: row r of CTA -> g_vf[idx-row], cols [ncb, ncb+128)
    {
        int r = tid >> 1;
        int half = (tid & 1) * 64;
        size_t grow = rowbase + r;
        int gpt = (int)(grow >> 4);
        int b = gpt >> 12;
        int j = g_idx[grow];
        const float* vp = g_vf + ((size_t)(b*NP + j))*256 + ncb + half;
        float* dst = Vs + r*VSTRIDE + half;
#pragma unroll
        for (int i=0;i<16;i++)
            *(float4*)(dst + i*4) = *(const float4*)(vp + i*4);
    }

    // softmax over K (16 rows per pt) — register + shfl only
#pragma unroll
    for (int mt=0;mt<2;mt++)
#pragma unroll
    for (int nt=0;nt<8;nt++){
        float a0=acc[mt][nt][0], a1=acc[mt][nt][1], a2=acc[mt][nt][2], a3=acc[mt][nt][3];
        float m0 = fmaxf(a0,a2), m1 = fmaxf(a1,a3);
#pragma unroll
        for (int mk=4; mk<=16; mk<<=1){
            m0 = fmaxf(m0, __shfl_xor_sync(0xffffffffu, m0, mk));
            m1 = fmaxf(m1, __shfl_xor_sync(0xffffffffu, m1, mk));
        }
        float e0=expf(a0-m0), e2=expf(a2-m0), e1=expf(a1-m1), e3=expf(a3-m1);
        float s0=e0+e2, s1=e1+e3;
#pragma unroll
        for (int mk=4; mk<=16; mk<<=1){
            s0 += __shfl_xor_sync(0xffffffffu, s0, mk);
            s1 += __shfl_xor_sync(0xffffffffu, s1, mk);
        }
        float i0=1.f/s0, i1=1.f/s1;
        acc[mt][nt][0]=e0*i0; acc[mt][nt][1]=e1*i1;
        acc[mt][nt][2]=e2*i0; acc[mt][nt][3]=e3*i1;
    }

    // u vectors for this thread's 2x2 k-rows
    float3 uv[2][2];
#pragma unroll
    for (int mt=0;mt<2;mt++)
#pragma unroll
    for (int kk=0;kk<2;kk++){
        size_t r = rowbase + wm*32 + mt*16 + g + kk*8;
        uv[mt][kk] = make_float3(g_u[r*3], g_u[r*3+1], g_u[r*3+2]);
    }

    __syncthreads();   // Vs ready

    // weighted output: out[pt][col] = sum_k attn * (v + pe)
#pragma unroll
    for (int nt=0;nt<8;nt++){
        int c0 = wn*64 + nt*8 + 2*t;       // local col
        int gc = ncb + c0;                  // global col
        float w0a=d2w[gc],   w1a=d2w[256+gc],   w2a=d2w[512+gc],   ba=d2b[gc];
        float w0b=d2w[gc+1], w1b=d2w[257+gc],   w2b=d2w[513+gc],   bb=d2b[gc+1];
#pragma unroll
        for (int mt=0;mt<2;mt++){
            float o0=0.f, o1=0.f;
#pragma unroll
            for (int kk=0;kk<2;kk++){
                int r = wm*32 + mt*16 + g + kk*8;
                float2 v = *(const float2*)&Vs[r*VSTRIDE + c0];
                float3 u = uv[mt][kk];
                float pea = u.x*w0a + u.y*w1a + u.z*w2a + ba;
                float peb = u.x*w0b + u.y*w1b + u.z*w2b + bb;
                o0 += acc[mt][nt][kk*2+0] * (v.x + pea);
                o1 += acc[mt][nt][kk*2+1] * (v.y + peb);
            }
#pragma unroll
            for (int mk=4; mk<=16; mk<<=1){
                o0 += __shfl_xor_sync(0xffffffffu, o0, mk);
                o1 += __shfl_xor_sync(0xffffffffu, o1, mk);
            }
            if (g == 0){
                size_t pt = (rowbase >> 4) + 2*wm + mt;
                *(float2*)&out[pt*256 + gc] = make_float2(o0, o1);
            }
        }
    }
}

// ---------------- finalize per-channel BN over 256 channels ----------------
__global__ __launch_bounds__(256) void bnfin_kernel(const float* __restrict__ psum,
                                                    const float* __restrict__ psq, int P,
                                                    const float* __restrict__ g,
                                                    const float* __restrict__ beta,
                                                    float* __restrict__ outp)
{
    int c = threadIdx.x;
    double s=0.0,q=0.0;
    for (int i=0;i<P;i++){ s+=psum[i*NC+c]; q+=psq[i*NC+c]; }
    double m = s/(double)NROWS;
    double v = q/(double)NROWS - m*m;
    double sc = (double)g[c] / sqrt(v+1e-5);
    outp[c]    = (float)sc;
    outp[NC+c] = (float)((double)beta[c] - m*sc);
}

// ---------------- h producer: h = q - k[idx] + pos_enc; fused bn1 stats ----------------
__global__ __launch_bounds__(256) void hprod_kernel(
    const float* __restrict__ xyz, const float* __restrict__ d1w, const float* __restrict__ d1b,
    const float* __restrict__ d2w, const float* __restrict__ d2b)
{
    __shared__ float su[NK*3];
    __shared__ int   sj[NK];
    int c = threadIdx.x;
    float d2c0 = d2w[c], d2c1 = d2w[256+c], d2c2 = d2w[512+c], d2bc = d2b[c];
    float s=0.f, q=0.f;
    for (int pp=0; pp<32; pp++){
        int pt = blockIdx.x*32 + pp;
        int b  = pt >> 12;
        if (c < NK){
            int k = c;
            int j = g_idx[pt*NK+k];
            sj[k]=j;
            float r0 = xyz[pt*3+0]-xyz[(b*NP+j)*3+0];
            float r1 = xyz[pt*3+1]-xyz[(b*NP+j)*3+1];
            float r2 = xyz[pt*3+2]-xyz[(b*NP+j)*3+2];
#pragma unroll
            for (int d=0;d<3;d++){
                float t  = r0*d1w[d] + r1*d1w[3+d] + r2*d1w[6+d] + d1b[d];
                float uu = fmaxf(0.f, fmaf(t, g_bnd[d], g_bnd[3+d]));
                su[k*3+d]=uu;
                g_u[(pt*NK+k)*3+d]=uu;
            }
        }
        __syncthreads();
        float qv = g_q[pt*NC + c];
#pragma unroll
        for (int k=0;k<NK;k++){
            int j = sj[k];
            float kv = g_kf[(b*NP+j)*NC + c];
            float pe = su[k*3]*d2c0 + su[k*3+1]*d2c1 + su[k*3+2]*d2c2 + d2bc;
            float h = qv - kv + pe;
            g_h[(size_t)(pt*NK+k)*NC + c] = h;
            s += h; q += h*h;
        }
        __syncthreads();
    }
    g_ps1[blockIdx.x*NC+c]=s;
    g_pq1[blockIdx.x*NC+c]=q;
}

// ---------------- host launcher (graph-capturable, allocation-free) ----------------
extern "C" void kernel_launch(void* const* d_in, const int* in_sizes, int n_in,
                              void* d_out, int out_size)
{
    const float* xyz  = (const float*)d_in[0];
    const float* feat = (const float*)d_in[1];
    const float* wq   = (const float*)d_in[2];  const float* bq  = (const float*)d_in[3];
    const float* wk   = (const float*)d_in[4];  const float* bk  = (const float*)d_in[5];
    const float* wv   = (const float*)d_in[6];  const float* bv  = (const float*)d_in[7];
    const float* d1w  = (const float*)d_in[8];  const float* d1b = (const float*)d_in[9];
    const float* bndg = (const float*)d_in[10]; const float* bndb= (const float*)d_in[11];
    const float* d2w  = (const float*)d_in[12]; const float* d2b = (const float*)d_in[13];
    const float* g1g  = (const float*)d_in[14]; const float* g1bt= (const float*)d_in[15];
    const float* g1w  = (const float*)d_in[16]; const float* g1b = (const float*)d_in[17];
    const float* g2g  = (const float*)d_in[18]; const float* g2bt= (const float*)d_in[19];
    const float* g2w  = (const float*)d_in[20]; const float* g2b = (const float*)d_in[21];
    float* out = (float*)d_out;

    float *p_q,*p_kf,*p_vf,*p_h,*p_h2,*p_bn1,*p_bn2,*p_ps1,*p_pq1,*p_ps2,*p_pq2;
    __nv_bfloat16 *p_bh1,*p_bl1,*p_bh2,*p_bl2,*p_bhq,*p_blq,*p_bhk,*p_blk,*p_bhv,*p_blv;
    cudaGetSymbolAddress((void**)&p_q,  g_q);
    cudaGetSymbolAddress((void**)&p_kf, g_kf);
    cudaGetSymbolAddress((void**)&p_vf, g_vf);
    cudaGetSymbolAddress((void**)&p_h,  g_h);
    cudaGetSymbolAddress((void**)&p_h2, g_h2);
    cudaGetSymbolAddress((void**)&p_bn1,g_bn1);
    cudaGetSymbolAddress((void**)&p_bn2,g_bn2);
    cudaGetSymbolAddress((void**)&p_ps1,g_ps1);
    cudaGetSymbolAddress((void**)&p_pq1,g_pq1);
    cudaGetSymbolAddress((void**)&p_ps2,g_ps2);
    cudaGetSymbolAddress((void**)&p_pq2,g_pq2);
    cudaGetSymbolAddress((void**)&p_bh1,g_bh1);
    cudaGetSymbolAddress((void**)&p_bl1,g_bl1);
    cudaGetSymbolAddress((void**)&p_bh2,g_bh2);
    cudaGetSymbolAddress((void**)&p_bl2,g_bl2);
    cudaGetSymbolAddress((void**)&p_bhq,g_bhq);
    cudaGetSymbolAddress((void**)&p_blq,g_blq);
    cudaGetSymbolAddress((void**)&p_bhk,g_bhk);
    cudaGetSymbolAddress((void**)&p_blk,g_blk);
    cudaGetSymbolAddress((void**)&p_bhv,g_bhv);
    cudaGetSymbolAddress((void**)&p_blv,g_blv);

    cudaFuncSetAttribute(gemm_attn_kernel,
                         cudaFuncAttributeMaxDynamicSharedMemorySize, 128*VSTRIDE*4);

    // 1. KNN indices
    knn_kernel<<<dim3(NP/16, NB), 512>>>(xyz);
    // 2. d-path BN stats + finalize; all weight splits in ONE launch
    dstat_kernel<<<512,256>>>(xyz, d1w, d1b);
    dfin_kernel<<<1,32>>>(bndg, bndb);
    bprep5_kernel<<<dim3(NC,5),NC>>>(g1w, g2w, wq, wk, wv);
    // 3. q / k / v projections (HMMA bf16x3)
    gemm_mma_kernel<false,false><<<dim3(NPTS/128,2),256>>>(feat, p_bhq, p_blq, bq, nullptr, p_q,  nullptr, nullptr);
    gemm_mma_kernel<false,false><<<dim3(NPTS/128,2),256>>>(feat, p_bhk, p_blk, bk, nullptr, p_kf, nullptr, nullptr);
    gemm_mma_kernel<false,false><<<dim3(NPTS/128,2),256>>>(feat, p_bhv, p_blv, bv, nullptr, p_vf, nullptr, nullptr);
    // 4. h = q - k[idx] + pos_enc (stores u, fused bn1 stats)
    hprod_kernel<<<512,256>>>(xyz, d1w, d1b, d2w, d2b);
    bnfin_kernel<<<1,256>>>(p_ps1, p_pq1, 512, g1g, g1bt, p_bn1);
    // 5. gamma layer 1 (HMMA): relu(bn1(h)) @ g1_w + g1_b -> h2, fused bn2 stats
    gemm_mma_kernel<true,true><<<dim3(NROWS/128,2),256>>>(p_h, p_bh1, p_bl1, g1b, p_bn1, p_h2, p_ps2, p_pq2);
    bnfin_kernel<<<1,256>>>(p_ps2, p_pq2, 2048, g2g, g2bt, p_bn2);
    // 6. FUSED gamma layer 2 + softmax(K) + weighted output (no attn round trip)
    gemm_attn_kernel<<<dim3(NROWS/128,2),256,128*VSTRIDE*4>>>(
        p_h2, p_bh2, p_bl2, g2b, p_bn2, d2w, d2b, out);
}

// round 11
// speedup vs baseline: 1.0546x; 1.0335x over previous
#include <cuda_runtime.h>
#include <cuda_bf16.h>
#include <math.h>
#include <float.h>

#define NB 4
#define NP 4096
#define NC 256
#define NK 16
#define NPTS (NB*NP)      /* 16384 */
#define NROWS (NPTS*NK)   /* 262144 */

// ---------------- scratch (device globals; no allocation) ----------------
__device__ float g_q [NPTS*NC];
__device__ float g_kf[NPTS*NC];
__device__ float g_vf[NPTS*NC];
__device__ int   g_idx[NROWS];
__device__ float g_u [NROWS*3];
__device__ float g_h [NROWS*NC];
__device__ float g_h2[NROWS*NC];
__device__ float g_bnd[6];         // scale[3], shift[3] for d-path BN
__device__ float g_partd[512*6];
__device__ float g_ps1[512*NC];
__device__ float g_pq1[512*NC];
__device__ float g_ps2[2048*NC];
__device__ float g_pq2[2048*NC];
__device__ float g_bn1[2*NC];
__device__ float g_bn2[2*NC];
// bf16 hi/lo split weights, [n][k] layout (n = output col, k = input channel)
__device__ __nv_bfloat16 g_bh1[NC*NC], g_bl1[NC*NC];
__device__ __nv_bfloat16 g_bh2[NC*NC], g_bl2[NC*NC];
__device__ __nv_bfloat16 g_bhq[NC*NC], g_blq[NC*NC];
__device__ __nv_bfloat16 g_bhk[NC*NC], g_blk[NC*NC];
__device__ __nv_bfloat16 g_bhv[NC*NC], g_blv[NC*NC];

// ---------------- exact-rounding helpers for KNN ----------------
__device__ __forceinline__ float sq3_exact(float x, float y, float z){
    return __fadd_rn(__fadd_rn(__fmul_rn(x,x), __fmul_rn(y,y)), __fmul_rn(z,z));
}
__device__ __forceinline__ float dist_exact(float qx,float qy,float qz,float qw,
                                            float px,float py,float pz,float pw){
    float dot = __fmaf_rn(qz, pz, __fmaf_rn(qy, py, __fmul_rn(qx, px)));
    return __fsub_rn(__fadd_rn(qw, pw), __fmul_rn(2.0f, dot));
}

// ---------------- KNN: one warp per query, chunked smem points ----------------
__global__ __launch_bounds__(512) void knn_kernel(const float* __restrict__ xyz)
{
    constexpr int CH = 2048;
    __shared__ float4 pts[CH];
    int b = blockIdx.y;
    const float* xb = xyz + b*NP*3;
    int warp = threadIdx.x >> 5, lane = threadIdx.x & 31;
    int n = blockIdx.x*16 + warp;
    float qx = xb[n*3+0], qy = xb[n*3+1], qz = xb[n*3+2];
    float qw = sq3_exact(qx, qy, qz);
    float dl[NK]; int il[NK];
#pragma unroll
    for (int j=0;j<NK;j++){ dl[j]=FLT_MAX; il[j]=0x7fffffff; }

    for (int c0=0;c0<NP;c0+=CH){
        __syncthreads();
        for (int i=threadIdx.x;i<CH;i+=512){
            int m=c0+i;
            float x=xb[m*3],y=xb[m*3+1],z=xb[m*3+2];
            pts[i]=make_float4(x,y,z, sq3_exact(x,y,z));
        }
        __syncthreads();
        for (int i=lane;i<CH;i+=32){
            float4 p=pts[i];
            int m=c0+i;
            float d = dist_exact(qx,qy,qz,qw, p.x,p.y,p.z,p.w);
            if (d < dl[NK-1] || (d==dl[NK-1] && m<il[NK-1])){
                dl[NK-1]=d; il[NK-1]=m;
#pragma unroll
                for (int j=NK-1;j>0;j--){
                    bool sw = dl[j]<dl[j-1] || (dl[j]==dl[j-1] && il[j]<il[j-1]);
                    float t0 = sw? dl[j-1]:dl[j];
                    float t1 = sw? dl[j]:dl[j-1];
                    int   i0 = sw? il[j-1]:il[j];
                    int   i1 = sw? il[j]:il[j-1];
                    dl[j]=t0; dl[j-1]=t1; il[j]=i0; il[j-1]=i1;
                }
            }
        }
    }
    for (int r=0;r<NK;r++){
        float cd = dl[0]; int ci = il[0];
        float rd = cd;    int ri = ci;
#pragma unroll
        for (int off=16; off>0; off>>=1){
            float od = __shfl_down_sync(0xffffffffu, rd, off);
            int   oi = __shfl_down_sync(0xffffffffu, ri, off);
            if (od<rd || (od==rd && oi<ri)){ rd=od; ri=oi; }
        }
        rd = __shfl_sync(0xffffffffu, rd, 0);
        ri = __shfl_sync(0xffffffffu, ri, 0);
        if (lane==0) g_idx[(b*NP+n)*NK + r] = ri;
        if (cd==rd && ci==ri){
#pragma unroll
            for (int j=0;j<NK-1;j++){ dl[j]=dl[j+1]; il[j]=il[j+1]; }
            dl[NK-1]=FLT_MAX; il[NK-1]=0x7fffffff;
        }
    }
}

// ---------------- d-path BN stats ----------------
__global__ __launch_bounds__(256) void dstat_kernel(const float* __restrict__ xyz,
                                                    const float* __restrict__ d1w,
                                                    const float* __restrict__ d1b)
{
    float s[3]={0.f,0.f,0.f}, sq[3]={0.f,0.f,0.f};
    int stride = gridDim.x*blockDim.x;
    for (int it = blockIdx.x*blockDim.x+threadIdx.x; it < NROWS; it += stride){
        int pt = it >> 4;
        int b  = pt >> 12;
        int j  = g_idx[it];
        float r0 = xyz[pt*3+0] - xyz[(b*NP+j)*3+0];
        float r1 = xyz[pt*3+1] - xyz[(b*NP+j)*3+1];
        float r2 = xyz[pt*3+2] - xyz[(b*NP+j)*3+2];
#pragma unroll
        for (int d=0;d<3;d++){
            float t = r0*d1w[d] + r1*d1w[3+d] + r2*d1w[6+d] + d1b[d];
            s[d]+=t; sq[d]+=t*t;
        }
    }
    __shared__ float red[256];
    for (int q=0;q<6;q++){
        red[threadIdx.x] = (q<3)? s[q] : sq[q-3];
        __syncthreads();
        for (int st=128; st; st>>=1){
            if (threadIdx.x<st) red[threadIdx.x]+=red[threadIdx.x+st];
            __syncthreads();
        }
        if (threadIdx.x==0) g_partd[blockIdx.x*6+q]=red[0];
        __syncthreads();
    }
}

__global__ void dfin_kernel(const float* __restrict__ g, const float* __restrict__ beta)
{
    int d = threadIdx.x;
    if (d>=3) return;
    double s=0.0,q=0.0;
    for (int i=0;i<512;i++){ s+=g_partd[i*6+d]; q+=g_partd[i*6+3+d]; }
    double m = s/(double)NROWS;
    double v = q/(double)NROWS - m*m;
    double sc = (double)g[d] / sqrt(v+1e-5);
    g_bnd[d]   = (float)sc;
    g_bnd[3+d] = (float)((double)beta[d] - m*sc);
}

// ---------------- weight prep (all 5 matrices, one launch) ----------------
__global__ void bprep5_kernel(const float* __restrict__ g1w, const float* __restrict__ g2w,
                              const float* __restrict__ wq,  const float* __restrict__ wk,
                              const float* __restrict__ wv)
{
    int k = blockIdx.x, n = threadIdx.x;
    const float* W; __nv_bfloat16 *H, *L;
    switch (blockIdx.y){
        case 0: W=g1w; H=g_bh1; L=g_bl1; break;
        case 1: W=g2w; H=g_bh2; L=g_bl2; break;
        case 2: W=wq;  H=g_bhq; L=g_blq; break;
        case 3: W=wk;  H=g_bhk; L=g_blk; break;
        default:W=wv;  H=g_bhv; L=g_blv; break;
    }
    float w = W[k*NC+n];
    __nv_bfloat16 h = __float2bfloat16_rn(w);
    H[n*NC+k] = h;
    L[n*NC+k] = __float2bfloat16_rn(w - __bfloat162float(h));
}

// ---------------- HMMA helpers ----------------
__device__ __forceinline__ void mma_bf16(float* c, const unsigned* a, const unsigned* b){
    asm volatile(
      "mma.sync.aligned.m16n8k16.row.col.f32.bf16.bf16.f32 "
      "{%0,%1,%2,%3}, {%4,%5,%6,%7}, {%8,%9}, {%0,%1,%2,%3};"
      : "+f"(c[0]),"+f"(c[1]),"+f"(c[2]),"+f"(c[3])
      : "r"(a[0]),"r"(a[1]),"r"(a[2]),"r"(a[3]), "r"(b[0]),"r"(b[1]));
}
__device__ __forceinline__ void ldmx4(unsigned* r, unsigned addr){
    asm volatile("ldmatrix.sync.aligned.m8n8.x4.shared.b16 {%0,%1,%2,%3}, [%4];"
                 : "=r"(r[0]),"=r"(r[1]),"=r"(r[2]),"=r"(r[3]) : "r"(addr));
}

#define KC 32           /* K-chunk */
#define RSTRIDE 40      /* row stride in halves: 80B, ldmatrix conflict-free */
#define TILE_BYTES (128*RSTRIDE*2)

// Shared mainloop: stages f(A) (bf16 hi/lo) and W (hi/lo) tiles, 3 HMMA passes.
// Fragments loaded via ldmatrix.x4 (6 per k-step vs 24 scalar LDS).
template<bool BNRELU>
__device__ __forceinline__ void gemm_mainloop(
    const float* __restrict__ A, const __nv_bfloat16* __restrict__ Bh,
    const __nv_bfloat16* __restrict__ Bl, const float* __restrict__ bnp,
    unsigned short (*AsH)[RSTRIDE], unsigned short (*AsL)[RSTRIDE],
    unsigned short (*BsH)[RSTRIDE], unsigned short (*BsL)[RSTRIDE],
    size_t rowbase, int ncb, int tid, int g, int t, int wm, int wn,
    float acc[2][8][4])
{
    int lane = tid & 31;
    int lr = tid >> 1;
    int cg = (tid & 1) * 16;
    // ldmatrix per-lane address offsets (bytes, within a tile)
    int q3 = lane >> 3, rl = lane & 7;
    unsigned aoffA = (unsigned)(((wm*32 + (q3&1)*8 + rl) * RSTRIDE + (q3>>1)*8) * 2);
    unsigned aoffB = (unsigned)(((wn*64 + (q3>>1)*8 + rl) * RSTRIDE + (q3&1)*8) * 2);
    unsigned aAH = (unsigned)__cvta_generic_to_shared(AsH);
    unsigned aAL = (unsigned)__cvta_generic_to_shared(AsL);
    unsigned aBH = (unsigned)__cvta_generic_to_shared(BsH);
    unsigned aBL = (unsigned)__cvta_generic_to_shared(BsL);

    for (int kc0 = 0; kc0 < 256; kc0 += KC){
        if (kc0) __syncthreads();
        {
            const float* ap = A + (rowbase + lr)*256 + kc0 + cg;
            float v[16];
            *(float4*)(v)    = *(const float4*)(ap);
            *(float4*)(v+4)  = *(const float4*)(ap+4);
            *(float4*)(v+8)  = *(const float4*)(ap+8);
            *(float4*)(v+12) = *(const float4*)(ap+12);
            unsigned hh[8], ll[8];
#pragma unroll
            for (int p=0;p<8;p++){
                float a0 = v[p*2], a1 = v[p*2+1];
                if (BNRELU){
                    int c = kc0 + cg + p*2;
                    a0 = fmaxf(0.f, fmaf(a0, bnp[c],   bnp[256+c]));
                    a1 = fmaxf(0.f, fmaf(a1, bnp[c+1], bnp[257+c]));
                }
                __nv_bfloat16 h0 = __float2bfloat16_rn(a0);
                __nv_bfloat16 h1 = __float2bfloat16_rn(a1);
                __nv_bfloat16 l0 = __float2bfloat16_rn(a0 - __bfloat162float(h0));
                __nv_bfloat16 l1 = __float2bfloat16_rn(a1 - __bfloat162float(h1));
                hh[p] = (unsigned)__bfloat16_as_ushort(h0) | ((unsigned)__bfloat16_as_ushort(h1)<<16);
                ll[p] = (unsigned)__bfloat16_as_ushort(l0) | ((unsigned)__bfloat16_as_ushort(l1)<<16);
            }
            *(uint4*)&AsH[lr][cg]   = make_uint4(hh[0],hh[1],hh[2],hh[3]);
            *(uint4*)&AsH[lr][cg+8] = make_uint4(hh[4],hh[5],hh[6],hh[7]);
            *(uint4*)&AsL[lr][cg]   = make_uint4(ll[0],ll[1],ll[2],ll[3]);
            *(uint4*)&AsL[lr][cg+8] = make_uint4(ll[4],ll[5],ll[6],ll[7]);
        }
        {
            const __nv_bfloat16* bhp = Bh + (size_t)(ncb + lr)*256 + kc0 + cg;
            const __nv_bfloat16* blp = Bl + (size_t)(ncb + lr)*256 + kc0 + cg;
            *(uint4*)&BsH[lr][cg]   = *(const uint4*)(bhp);
            *(uint4*)&BsH[lr][cg+8] = *(const uint4*)(bhp+8);
            *(uint4*)&BsL[lr][cg]   = *(const uint4*)(blp);
            *(uint4*)&BsL[lr][cg+8] = *(const uint4*)(blp+8);
        }
        __syncthreads();
#pragma unroll
        for (int p=0;p<3;p++){
            unsigned Abase = (p==2)? aAL : aAH;
            unsigned Bbase = (p==1)? aBL : aBH;
#pragma unroll
            for (int ks=0; ks<KC; ks+=16){
                unsigned af[2][4];
#pragma unroll
                for (int mt=0;mt<2;mt++)
                    ldmx4(af[mt], Abase + aoffA + (unsigned)((mt*16*RSTRIDE + ks)*2));
#pragma unroll
                for (int ntp=0;ntp<4;ntp++){
                    unsigned bb[4];
                    ldmx4(bb, Bbase + aoffB + (unsigned)((ntp*16*RSTRIDE + ks)*2));
                    mma_bf16(acc[0][2*ntp],   af[0], bb);
                    mma_bf16(acc[1][2*ntp],   af[1], bb);
                    mma_bf16(acc[0][2*ntp+1], af[0], bb+2);
                    mma_bf16(acc[1][2*ntp+1], af[1], bb+2);
                }
            }
        }
    }
}

// ---------------- GEMM (qkv / gamma1): store C, optional BN+fused stats ----------------
template<bool BNRELU, bool STATS>
__global__ __launch_bounds__(256, 2) void gemm_mma_kernel(
    const float* __restrict__ A,
    const __nv_bfloat16* __restrict__ Bh, const __nv_bfloat16* __restrict__ Bl,
    const float* __restrict__ bias, const float* __restrict__ bnp,
    float* __restrict__ C, float* __restrict__ psum, float* __restrict__ psq)
{
    __shared__ __align__(16) unsigned short AsH[128][RSTRIDE];
    __shared__ __align__(16) unsigned short AsL[128][RSTRIDE];
    __shared__ __align__(16) unsigned short BsH[128][RSTRIDE];
    __shared__ __align__(16) unsigned short BsL[128][RSTRIDE];

    int tid = threadIdx.x, wid = tid >> 5, lane = tid & 31;
    int g = lane >> 2, t = lane & 3;
    int wm = wid & 3, wn = wid >> 2;
    const size_t rowbase = (size_t)blockIdx.x * 128;
    const int ncb = blockIdx.y * 128;

    float acc[2][8][4];
#pragma unroll
    for (int mt=0;mt<2;mt++)
#pragma unroll
        for (int nt=0;nt<8;nt++)
#pragma unroll
            for (int i=0;i<4;i++) acc[mt][nt][i]=0.f;

    gemm_mainloop<BNRELU>(A, Bh, Bl, bnp, AsH, AsL, BsH, BsL,
                          rowbase, ncb, tid, g, t, wm, wn, acc);

#pragma unroll
    for (int nt=0;nt<8;nt++){
        int col = ncb + wn*64 + nt*8 + 2*t;
        float b0 = bias[col], b1 = bias[col+1];
#pragma unroll
        for (int mt=0;mt<2;mt++){
            acc[mt][nt][0]+=b0; acc[mt][nt][1]+=b1;
            acc[mt][nt][2]+=b0; acc[mt][nt][3]+=b1;
        }
    }
#pragma unroll
    for (int nt=0;nt<8;nt++){
        int col = ncb + wn*64 + nt*8 + 2*t;
#pragma unroll
        for (int mt=0;mt<2;mt++){
            size_t row = rowbase + wm*32 + mt*16 + g;
            *(float2*)&C[row*256 + col]     = make_float2(acc[mt][nt][0], acc[mt][nt][1]);
            *(float2*)&C[(row+8)*256 + col] = make_float2(acc[mt][nt][2], acc[mt][nt][3]);
        }
    }

    if (STATS){
        __syncthreads();
        float* sS = (float*)AsH;              // [4][128]
        float* sQ = sS + 512;
#pragma unroll
        for (int nt=0;nt<8;nt++){
            float s0=0.f,q0=0.f,s1=0.f,q1=0.f;
#pragma unroll
            for (int mt=0;mt<2;mt++){
                float v0=acc[mt][nt][0], v2=acc[mt][nt][2];
                float v1=acc[mt][nt][1], v3=acc[mt][nt][3];
                s0 += v0+v2;  q0 += v0*v0+v2*v2;
                s1 += v1+v3;  q1 += v1*v1+v3*v3;
            }
#pragma unroll
            for (int off=16; off>=4; off>>=1){
                s0 += __shfl_down_sync(0xffffffffu, s0, off);
                q0 += __shfl_down_sync(0xffffffffu, q0, off);
                s1 += __shfl_down_sync(0xffffffffu, s1, off);
                q1 += __shfl_down_sync(0xffffffffu, q1, off);
            }
            if (lane < 4){
                int c = wn*64 + nt*8 + 2*lane;
                sS[wm*128 + c]     = s0;  sS[wm*128 + c + 1] = s1;
                sQ[wm*128 + c]     = q0;  sQ[wm*128 + c + 1] = q1;
            }
        }
        __syncthreads();
        if (tid < 128){
            float s = sS[tid] + sS[128+tid] + sS[256+tid] + sS[384+tid];
            float q = sQ[tid] + sQ[128+tid] + sQ[256+tid] + sQ[384+tid];
            psum[blockIdx.x*256 + ncb + tid] = s;
            psq [blockIdx.x*256 + ncb + tid] = q;
        }
    }
}

// ---------------- fused gamma2 + softmax(K) + weighted output ----------------
#define VSTRIDE 132
__global__ __launch_bounds__(256, 2) void gemm_attn_kernel(
    const float* __restrict__ A,
    const __nv_bfloat16* __restrict__ Bh, const __nv_bfloat16* __restrict__ Bl,
    const float* __restrict__ bias, const float* __restrict__ bnp,
    const float* __restrict__ d2w, const float* __restrict__ d2b,
    float* __restrict__ out)
{
    extern __shared__ __align__(16) char dsm[];
    unsigned short (*AsH)[RSTRIDE] = (unsigned short(*)[RSTRIDE])(dsm);
    unsigned short (*AsL)[RSTRIDE] = (unsigned short(*)[RSTRIDE])(dsm + TILE_BYTES);
    unsigned short (*BsH)[RSTRIDE] = (unsigned short(*)[RSTRIDE])(dsm + 2*TILE_BYTES);
    unsigned short (*BsL)[RSTRIDE] = (unsigned short(*)[RSTRIDE])(dsm + 3*TILE_BYTES);
    float* Vs = (float*)dsm;                     // reused after mainloop: 128 x VSTRIDE

    int tid = threadIdx.x, wid = tid >> 5, lane = tid & 31;
    int g = lane >> 2, t = lane & 3;
    int wm = wid & 3, wn = wid >> 2;
    const size_t rowbase = (size_t)blockIdx.x * 128;
    const int ncb = blockIdx.y * 128;

    float acc[2][8][4];
#pragma unroll
    for (int mt=0;mt<2;mt++)
#pragma unroll
        for (int nt=0;nt<8;nt++)
#pragma unroll
            for (int i=0;i<4;i++) acc[mt][nt][i]=0.f;

    gemm_mainloop<true>(A, Bh, Bl, bnp, AsH, AsL, BsH, BsL,
                        rowbase, ncb, tid, g, t, wm, wn, acc);

    // bias -> logits
#pragma unroll
    for (int nt=0;nt<8;nt++){
        int col = ncb + wn*64 + nt*8 + 2*t;
        float b0 = bias[col], b1 = bias[col+1];
#pragma unroll
        for (int mt=0;mt<2;mt++){
            acc[mt][nt][0]+=b0; acc[mt][nt][1]+=b1;
            acc[mt][nt][2]+=b0; acc[mt][nt][3]+=b1;
        }
    }

    __syncthreads();   // tiles no longer needed; reuse as Vs

    // stage gathered v rows
    {
        int r = tid >> 1;
        int half = (tid & 1) * 64;
        size_t grow = rowbase + r;
        int gpt = (int)(grow >> 4);
        int b = gpt >> 12;
        int j = g_idx[grow];
        const float* vp = g_vf + ((size_t)(b*NP + j))*256 + ncb + half;
        float* dst = Vs + r*VSTRIDE + half;
#pragma unroll
        for (int i=0;i<16;i++)
            *(float4*)(dst + i*4) = *(const float4*)(vp + i*4);
    }

    // softmax over K (16 rows per pt) — register + shfl only
#pragma unroll
    for (int mt=0;mt<2;mt++)
#pragma unroll
    for (int nt=0;nt<8;nt++){
        float a0=acc[mt][nt][0], a1=acc[mt][nt][1], a2=acc[mt][nt][2], a3=acc[mt][nt][3];
        float m0 = fmaxf(a0,a2), m1 = fmaxf(a1,a3);
#pragma unroll
        for (int mk=4; mk<=16; mk<<=1){
            m0 = fmaxf(m0, __shfl_xor_sync(0xffffffffu, m0, mk));
            m1 = fmaxf(m1, __shfl_xor_sync(0xffffffffu, m1, mk));
        }
        float e0=expf(a0-m0), e2=expf(a2-m0), e1=expf(a1-m1), e3=expf(a3-m1);
        float s0=e0+e2, s1=e1+e3;
#pragma unroll
        for (int mk=4; mk<=16; mk<<=1){
            s0 += __shfl_xor_sync(0xffffffffu, s0, mk);
            s1 += __shfl_xor_sync(0xffffffffu, s1, mk);
        }
        float i0=1.f/s0, i1=1.f/s1;
        acc[mt][nt][0]=e0*i0; acc[mt][nt][1]=e1*i1;
        acc[mt][nt][2]=e2*i0; acc[mt][nt][3]=e3*i1;
    }

    // u vectors for this thread's 2x2 k-rows
    float3 uv[2][2];
#pragma unroll
    for (int mt=0;mt<2;mt++)
#pragma unroll
    for (int kk=0;kk<2;kk++){
        size_t r = rowbase + wm*32 + mt*16 + g + kk*8;
        uv[mt][kk] = make_float3(g_u[r*3], g_u[r*3+1], g_u[r*3+2]);
    }

    __syncthreads();   // Vs ready

    // weighted output: out[pt][col] = sum_k attn * (v + pe)
#pragma unroll
    for (int nt=0;nt<8;nt++){
        int c0 = wn*64 + nt*8 + 2*t;
        int gc = ncb + c0;
        float w0a=d2w[gc],   w1a=d2w[256+gc],   w2a=d2w[512+gc],   ba=d2b[gc];
        float w0b=d2w[gc+1], w1b=d2w[257+gc],   w2b=d2w[513+gc],   bb=d2b[gc+1];
#pragma unroll
        for (int mt=0;mt<2;mt++){
            float o0=0.f, o1=0.f;
#pragma unroll
            for (int kk=0;kk<2;kk++){
                int r = wm*32 + mt*16 + g + kk*8;
                float2 v = *(const float2*)&Vs[r*VSTRIDE + c0];
                float3 u = uv[mt][kk];
                float pea = u.x*w0a + u.y*w1a + u.z*w2a + ba;
                float peb = u.x*w0b + u.y*w1b + u.z*w2b + bb;
                o0 += acc[mt][nt][kk*2+0] * (v.x + pea);
                o1 += acc[mt][nt][kk*2+1] * (v.y + peb);
            }
#pragma unroll
            for (int mk=4; mk<=16; mk<<=1){
                o0 += __shfl_xor_sync(0xffffffffu, o0, mk);
                o1 += __shfl_xor_sync(0xffffffffu, o1, mk);
            }
            if (g == 0){
                size_t pt = (rowbase >> 4) + 2*wm + mt;
                *(float2*)&out[pt*256 + gc] = make_float2(o0, o1);
            }
        }
    }
}

// ---------------- finalize per-channel BN over 256 channels ----------------
__global__ __launch_bounds__(256) void bnfin_kernel(const float* __restrict__ psum,
                                                    const float* __restrict__ psq, int P,
                                                    const float* __restrict__ g,
                                                    const float* __restrict__ beta,
                                                    float* __restrict__ outp)
{
    int c = threadIdx.x;
    double s=0.0,q=0.0;
    for (int i=0;i<P;i++){ s+=psum[i*NC+c]; q+=psq[i*NC+c]; }
    double m = s/(double)NROWS;
    double v = q/(double)NROWS - m*m;
    double sc = (double)g[c] / sqrt(v+1e-5);
    outp[c]    = (float)sc;
    outp[NC+c] = (float)((double)beta[c] - m*sc);
}

// ---------------- h producer: h = q - k[idx] + pos_enc; fused bn1 stats ----------------
__global__ __launch_bounds__(256) void hprod_kernel(
    const float* __restrict__ xyz, const float* __restrict__ d1w, const float* __restrict__ d1b,
    const float* __restrict__ d2w, const float* __restrict__ d2b)
{
    __shared__ float su[NK*3];
    __shared__ int   sj[NK];
    int c = threadIdx.x;
    float d2c0 = d2w[c], d2c1 = d2w[256+c], d2c2 = d2w[512+c], d2bc = d2b[c];
    float s=0.f, q=0.f;
    for (int pp=0; pp<32; pp++){
        int pt = blockIdx.x*32 + pp;
        int b  = pt >> 12;
        if (c < NK){
            int k = c;
            int j = g_idx[pt*NK+k];
            sj[k]=j;
            float r0 = xyz[pt*3+0]-xyz[(b*NP+j)*3+0];
            float r1 = xyz[pt*3+1]-xyz[(b*NP+j)*3+1];
            float r2 = xyz[pt*3+2]-xyz[(b*NP+j)*3+2];
#pragma unroll
            for (int d=0;d<3;d++){
                float t  = r0*d1w[d] + r1*d1w[3+d] + r2*d1w[6+d] + d1b[d];
                float uu = fmaxf(0.f, fmaf(t, g_bnd[d], g_bnd[3+d]));
                su[k*3+d]=uu;
                g_u[(pt*NK+k)*3+d]=uu;
            }
        }
        __syncthreads();
        float qv = g_q[pt*NC + c];
#pragma unroll
        for (int k=0;k<NK;k++){
            int j = sj[k];
            float kv = g_kf[(b*NP+j)*NC + c];
            float pe = su[k*3]*d2c0 + su[k*3+1]*d2c1 + su[k*3+2]*d2c2 + d2bc;
            float h = qv - kv + pe;
            g_h[(size_t)(pt*NK+k)*NC + c] = h;
            s += h; q += h*h;
        }
        __syncthreads();
    }
    g_ps1[blockIdx.x*NC+c]=s;
    g_pq1[blockIdx.x*NC+c]=q;
}

// ---------------- host launcher (graph-capturable, allocation-free) ----------------
extern "C" void kernel_launch(void* const* d_in, const int* in_sizes, int n_in,
                              void* d_out, int out_size)
{
    const float* xyz  = (const float*)d_in[0];
    const float* feat = (const float*)d_in[1];
    const float* wq   = (const float*)d_in[2];  const float* bq  = (const float*)d_in[3];
    const float* wk   = (const float*)d_in[4];  const float* bk  = (const float*)d_in[5];
    const float* wv   = (const float*)d_in[6];  const float* bv  = (const float*)d_in[7];
    const float* d1w  = (const float*)d_in[8];  const float* d1b = (const float*)d_in[9];
    const float* bndg = (const float*)d_in[10]; const float* bndb= (const float*)d_in[11];
    const float* d2w  = (const float*)d_in[12]; const float* d2b = (const float*)d_in[13];
    const float* g1g  = (const float*)d_in[14]; const float* g1bt= (const float*)d_in[15];
    const float* g1w  = (const float*)d_in[16]; const float* g1b = (const float*)d_in[17];
    const float* g2g  = (const float*)d_in[18]; const float* g2bt= (const float*)d_in[19];
    const float* g2w  = (const float*)d_in[20]; const float* g2b = (const float*)d_in[21];
    float* out = (float*)d_out;

    float *p_q,*p_kf,*p_vf,*p_h,*p_h2,*p_bn1,*p_bn2,*p_ps1,*p_pq1,*p_ps2,*p_pq2;
    __nv_bfloat16 *p_bh1,*p_bl1,*p_bh2,*p_bl2,*p_bhq,*p_blq,*p_bhk,*p_blk,*p_bhv,*p_blv;
    cudaGetSymbolAddress((void**)&p_q,  g_q);
    cudaGetSymbolAddress((void**)&p_kf, g_kf);
    cudaGetSymbolAddress((void**)&p_vf, g_vf);
    cudaGetSymbolAddress((void**)&p_h,  g_h);
    cudaGetSymbolAddress((void**)&p_h2, g_h2);
    cudaGetSymbolAddress((void**)&p_bn1,g_bn1);
    cudaGetSymbolAddress((void**)&p_bn2,g_bn2);
    cudaGetSymbolAddress((void**)&p_ps1,g_ps1);
    cudaGetSymbolAddress((void**)&p_pq1,g_pq1);
    cudaGetSymbolAddress((void**)&p_ps2,g_ps2);
    cudaGetSymbolAddress((void**)&p_pq2,g_pq2);
    cudaGetSymbolAddress((void**)&p_bh1,g_bh1);
    cudaGetSymbolAddress((void**)&p_bl1,g_bl1);
    cudaGetSymbolAddress((void**)&p_bh2,g_bh2);
    cudaGetSymbolAddress((void**)&p_bl2,g_bl2);
    cudaGetSymbolAddress((void**)&p_bhq,g_bhq);
    cudaGetSymbolAddress((void**)&p_blq,g_blq);
    cudaGetSymbolAddress((void**)&p_bhk,g_bhk);
    cudaGetSymbolAddress((void**)&p_blk,g_blk);
    cudaGetSymbolAddress((void**)&p_bhv,g_bhv);
    cudaGetSymbolAddress((void**)&p_blv,g_blv);

    cudaFuncSetAttribute(gemm_attn_kernel,
                         cudaFuncAttributeMaxDynamicSharedMemorySize, 128*VSTRIDE*4);

    // Launch order arranged so the 4th launch (ncu capture slot) is gemm_q (HMMA).
    // 1. weight splits (no deps)
    bprep5_kernel<<<dim3(NC,5),NC>>>(g1w, g2w, wq, wk, wv);
    // 2. KNN indices
    knn_kernel<<<dim3(NP/16, NB), 512>>>(xyz);
    // 3. d-path BN stats
    dstat_kernel<<<512,256>>>(xyz, d1w, d1b);
    // 4-6. q / k / v projections (HMMA bf16x3) — #4 gets profiled
    gemm_mma_kernel<false,false><<<dim3(NPTS/128,2),256>>>(feat, p_bhq, p_blq, bq, nullptr, p_q,  nullptr, nullptr);
    gemm_mma_kernel<false,false><<<dim3(NPTS/128,2),256>>>(feat, p_bhk, p_blk, bk, nullptr, p_kf, nullptr, nullptr);
    gemm_mma_kernel<false,false><<<dim3(NPTS/128,2),256>>>(feat, p_bhv, p_blv, bv, nullptr, p_vf, nullptr, nullptr);
    // 7. d-path BN finalize
    dfin_kernel<<<1,32>>>(bndg, bndb);
    // 8. h = q - k[idx] + pos_enc (stores u, fused bn1 stats)
    hprod_kernel<<<512,256>>>(xyz, d1w, d1b, d2w, d2b);
    bnfin_kernel<<<1,256>>>(p_ps1, p_pq1, 512, g1g, g1bt, p_bn1);
    // 9. gamma layer 1 (HMMA): relu(bn1(h)) @ g1_w + g1_b -> h2, fused bn2 stats
    gemm_mma_kernel<true,true><<<dim3(NROWS/128,2),256>>>(p_h, p_bh1, p_bl1, g1b, p_bn1, p_h2, p_ps2, p_pq2);
    bnfin_kernel<<<1,256>>>(p_ps2, p_pq2, 2048, g2g, g2bt, p_bn2);
    // 10. FUSED gamma layer 2 + softmax(K) + weighted output
    gemm_attn_kernel<<<dim3(NROWS/128,2),256,128*VSTRIDE*4>>>(
        p_h2, p_bh2, p_bl2, g2b, p_bn2, d2w, d2b, out);
}

// round 12
// speedup vs baseline: 1.0594x; 1.0046x over previous
#include <cuda_runtime.h>
#include <cuda_bf16.h>
#include <math.h>
#include <float.h>

#define NB 4
#define NP 4096
#define NC 256
#define NK 16
#define NPTS (NB*NP)      /* 16384 */
#define NROWS (NPTS*NK)   /* 262144 */

// ---------------- scratch (device globals; no allocation) ----------------
__device__ float g_q [NPTS*NC];
__device__ float g_kf[NPTS*NC];
__device__ float g_vf[NPTS*NC];
__device__ int   g_idx[NROWS];
__device__ float g_u [NROWS*3];
__device__ float g_h [NROWS*NC];
__device__ float g_h2[NROWS*NC];
__device__ float g_bnd[6];
__device__ float g_partd[512*6];
__device__ float g_ps1[512*NC];
__device__ float g_pq1[512*NC];
__device__ float g_ps2[2048*NC];
__device__ float g_pq2[2048*NC];
__device__ float g_bn1[2*NC];
__device__ float g_bn2[2*NC];
__device__ __nv_bfloat16 g_bh1[NC*NC], g_bl1[NC*NC];
__device__ __nv_bfloat16 g_bh2[NC*NC], g_bl2[NC*NC];
__device__ __nv_bfloat16 g_bhq[NC*NC], g_blq[NC*NC];
__device__ __nv_bfloat16 g_bhk[NC*NC], g_blk[NC*NC];
__device__ __nv_bfloat16 g_bhv[NC*NC], g_blv[NC*NC];

// ---------------- exact-rounding helpers for KNN ----------------
__device__ __forceinline__ float sq3_exact(float x, float y, float z){
    return __fadd_rn(__fadd_rn(__fmul_rn(x,x), __fmul_rn(y,y)), __fmul_rn(z,z));
}
__device__ __forceinline__ float dist_exact(float qx,float qy,float qz,float qw,
                                            float px,float py,float pz,float pw){
    float dot = __fmaf_rn(qz, pz, __fmaf_rn(qy, py, __fmul_rn(qx, px)));
    return __fsub_rn(__fadd_rn(qw, pw), __fmul_rn(2.0f, dot));
}

// ---------------- KNN ----------------
__global__ __launch_bounds__(512) void knn_kernel(const float* __restrict__ xyz)
{
    constexpr int CH = 2048;
    __shared__ float4 pts[CH];
    int b = blockIdx.y;
    const float* xb = xyz + b*NP*3;
    int warp = threadIdx.x >> 5, lane = threadIdx.x & 31;
    int n = blockIdx.x*16 + warp;
    float qx = xb[n*3+0], qy = xb[n*3+1], qz = xb[n*3+2];
    float qw = sq3_exact(qx, qy, qz);
    float dl[NK]; int il[NK];
#pragma unroll
    for (int j=0;j<NK;j++){ dl[j]=FLT_MAX; il[j]=0x7fffffff; }

    for (int c0=0;c0<NP;c0+=CH){
        __syncthreads();
        for (int i=threadIdx.x;i<CH;i+=512){
            int m=c0+i;
            float x=xb[m*3],y=xb[m*3+1],z=xb[m*3+2];
            pts[i]=make_float4(x,y,z, sq3_exact(x,y,z));
        }
        __syncthreads();
        for (int i=lane;i<CH;i+=32){
            float4 p=pts[i];
            int m=c0+i;
            float d = dist_exact(qx,qy,qz,qw, p.x,p.y,p.z,p.w);
            if (d < dl[NK-1] || (d==dl[NK-1] && m<il[NK-1])){
                dl[NK-1]=d; il[NK-1]=m;
#pragma unroll
                for (int j=NK-1;j>0;j--){
                    bool sw = dl[j]<dl[j-1] || (dl[j]==dl[j-1] && il[j]<il[j-1]);
                    float t0 = sw? dl[j-1]:dl[j];
                    float t1 = sw? dl[j]:dl[j-1];
                    int   i0 = sw? il[j-1]:il[j];
                    int   i1 = sw? il[j]:il[j-1];
                    dl[j]=t0; dl[j-1]=t1; il[j]=i0; il[j-1]=i1;
                }
            }
        }
    }
    for (int r=0;r<NK;r++){
        float cd = dl[0]; int ci = il[0];
        float rd = cd;    int ri = ci;
#pragma unroll
        for (int off=16; off>0; off>>=1){
            float od = __shfl_down_sync(0xffffffffu, rd, off);
            int   oi = __shfl_down_sync(0xffffffffu, ri, off);
            if (od<rd || (od==rd && oi<ri)){ rd=od; ri=oi; }
        }
        rd = __shfl_sync(0xffffffffu, rd, 0);
        ri = __shfl_sync(0xffffffffu, ri, 0);
        if (lane==0) g_idx[(b*NP+n)*NK + r] = ri;
        if (cd==rd && ci==ri){
#pragma unroll
            for (int j=0;j<NK-1;j++){ dl[j]=dl[j+1]; il[j]=il[j+1]; }
            dl[NK-1]=FLT_MAX; il[NK-1]=0x7fffffff;
        }
    }
}

// ---------------- d-path BN stats ----------------
__global__ __launch_bounds__(256) void dstat_kernel(const float* __restrict__ xyz,
                                                    const float* __restrict__ d1w,
                                                    const float* __restrict__ d1b)
{
    float s[3]={0.f,0.f,0.f}, sq[3]={0.f,0.f,0.f};
    int stride = gridDim.x*blockDim.x;
    for (int it = blockIdx.x*blockDim.x+threadIdx.x; it < NROWS; it += stride){
        int pt = it >> 4;
        int b  = pt >> 12;
        int j  = g_idx[it];
        float r0 = xyz[pt*3+0] - xyz[(b*NP+j)*3+0];
        float r1 = xyz[pt*3+1] - xyz[(b*NP+j)*3+1];
        float r2 = xyz[pt*3+2] - xyz[(b*NP+j)*3+2];
#pragma unroll
        for (int d=0;d<3;d++){
            float t = r0*d1w[d] + r1*d1w[3+d] + r2*d1w[6+d] + d1b[d];
            s[d]+=t; sq[d]+=t*t;
        }
    }
    __shared__ float red[256];
    for (int q=0;q<6;q++){
        red[threadIdx.x] = (q<3)? s[q] : sq[q-3];
        __syncthreads();
        for (int st=128; st; st>>=1){
            if (threadIdx.x<st) red[threadIdx.x]+=red[threadIdx.x+st];
            __syncthreads();
        }
        if (threadIdx.x==0) g_partd[blockIdx.x*6+q]=red[0];
        __syncthreads();
    }
}

__global__ void dfin_kernel(const float* __restrict__ g, const float* __restrict__ beta)
{
    int d = threadIdx.x;
    if (d>=3) return;
    double s=0.0,q=0.0;
    for (int i=0;i<512;i++){ s+=g_partd[i*6+d]; q+=g_partd[i*6+3+d]; }
    double m = s/(double)NROWS;
    double v = q/(double)NROWS - m*m;
    double sc = (double)g[d] / sqrt(v+1e-5);
    g_bnd[d]   = (float)sc;
    g_bnd[3+d] = (float)((double)beta[d] - m*sc);
}

// ---------------- weight prep (all 5 matrices, one launch) ----------------
__global__ void bprep5_kernel(const float* __restrict__ g1w, const float* __restrict__ g2w,
                              const float* __restrict__ wq,  const float* __restrict__ wk,
                              const float* __restrict__ wv)
{
    int k = blockIdx.x, n = threadIdx.x;
    const float* W; __nv_bfloat16 *H, *L;
    switch (blockIdx.y){
        case 0: W=g1w; H=g_bh1; L=g_bl1; break;
        case 1: W=g2w; H=g_bh2; L=g_bl2; break;
        case 2: W=wq;  H=g_bhq; L=g_blq; break;
        case 3: W=wk;  H=g_bhk; L=g_blk; break;
        default:W=wv;  H=g_bhv; L=g_blv; break;
    }
    float w = W[k*NC+n];
    __nv_bfloat16 h = __float2bfloat16_rn(w);
    H[n*NC+k] = h;
    L[n*NC+k] = __float2bfloat16_rn(w - __bfloat162float(h));
}

// ---------------- HMMA helpers ----------------
__device__ __forceinline__ void mma_bf16(float* c, const unsigned* a, const unsigned* b){
    asm volatile(
      "mma.sync.aligned.m16n8k16.row.col.f32.bf16.bf16.f32 "
      "{%0,%1,%2,%3}, {%4,%5,%6,%7}, {%8,%9}, {%0,%1,%2,%3};"
      : "+f"(c[0]),"+f"(c[1]),"+f"(c[2]),"+f"(c[3])
      : "r"(a[0]),"r"(a[1]),"r"(a[2]),"r"(a[3]), "r"(b[0]),"r"(b[1]));
}
__device__ __forceinline__ void ldmx4(unsigned* r, unsigned addr){
    asm volatile("ldmatrix.sync.aligned.m8n8.x4.shared.b16 {%0,%1,%2,%3}, [%4];"
                 : "=r"(r[0]),"=r"(r[1]),"=r"(r[2]),"=r"(r[3]) : "r"(addr));
}
__device__ __forceinline__ void cpa16(unsigned dst, const void* src){
    asm volatile("cp.async.cg.shared.global [%0], [%1], 16;" :: "r"(dst), "l"(src));
}
#define CPA_COMMIT asm volatile("cp.async.commit_group;" ::: "memory")
#define CPA_WAIT0  asm volatile("cp.async.wait_group 0;" ::: "memory")

#define KC 32           /* K-chunk */
#define RSTRIDE 40      /* bf16 tile row stride in halves: 80B, ldmatrix conflict-free */
#define ATILE 10240     /* bytes per 128xKC bf16 tile */
#define AFSTRIDE 36     /* fp32 A staging row stride in words (conflict-free LDS.128) */
// dynamic smem layout
#define SM_ASH 0
#define SM_ASL ATILE
#define SM_BH(buf) (2*ATILE + (buf)*2*ATILE)
#define SM_BL(buf) (3*ATILE + (buf)*2*ATILE)
#define SM_AF(buf) (6*ATILE + (buf)*(128*AFSTRIDE*4))
#define SM_TOTAL (6*ATILE + 2*(128*AFSTRIDE*4))   /* 98304 */

// Shared mainloop: cp.async double-buffered pipeline.
// Per chunk: wait -> bar -> issue next chunk -> convert A (smem fp32 -> bf16 hi/lo)
// -> bar -> 3 HMMA passes via ldmatrix.
template<bool BNRELU>
__device__ __forceinline__ void gemm_mainloop(
    const float* __restrict__ A, const __nv_bfloat16* __restrict__ Bh,
    const __nv_bfloat16* __restrict__ Bl, const float* __restrict__ bnp,
    char* dsm, size_t rowbase, int ncb, int tid, int wm, int wn,
    float acc[2][8][4])
{
    int lane = tid & 31;
    int lr = tid >> 1;
    int cg = (tid & 1) * 16;
    int q3 = lane >> 3, rl = lane & 7;
    unsigned sb = (unsigned)__cvta_generic_to_shared(dsm);
    unsigned aoffA = (unsigned)(((wm*32 + (q3&1)*8 + rl) * RSTRIDE + (q3>>1)*8) * 2);
    unsigned aoffB = (unsigned)(((wn*64 + (q3>>1)*8 + rl) * RSTRIDE + (q3&1)*8) * 2);

    const float*         asrc0 = A  + (rowbase + lr)*256 + cg;
    const __nv_bfloat16* bhs0  = Bh + (size_t)(ncb + lr)*256 + cg;
    const __nv_bfloat16* bls0  = Bl + (size_t)(ncb + lr)*256 + cg;
    unsigned adst_r = (unsigned)((lr*AFSTRIDE + cg)*4);
    unsigned bdst_r = (unsigned)((lr*RSTRIDE  + cg)*2);

    // prologue: chunk 0 -> buffers 0
    {
        unsigned ad = sb + SM_AF(0) + adst_r;
        cpa16(ad,    asrc0);     cpa16(ad+16, asrc0+4);
        cpa16(ad+32, asrc0+8);   cpa16(ad+48, asrc0+12);
        unsigned bh = sb + SM_BH(0) + bdst_r;
        unsigned bl = sb + SM_BL(0) + bdst_r;
        cpa16(bh, bhs0); cpa16(bh+16, bhs0+8);
        cpa16(bl, bls0); cpa16(bl+16, bls0+8);
        CPA_COMMIT;
    }

    for (int ic = 0; ic < 8; ic++){
        int buf = ic & 1;
        CPA_WAIT0;
        __syncthreads();                 // chunk ic data visible; compute ic-1 done everywhere

        if (ic < 7){                     // issue chunk ic+1 into alternate buffers
            int kc1 = (ic+1)*KC;
            unsigned ad = sb + SM_AF(buf^1) + adst_r;
            const float* as = asrc0 + kc1;
            cpa16(ad,    as);    cpa16(ad+16, as+4);
            cpa16(ad+32, as+8);  cpa16(ad+48, as+12);
            unsigned bh = sb + SM_BH(buf^1) + bdst_r;
            unsigned bl = sb + SM_BL(buf^1) + bdst_r;
            cpa16(bh, bhs0 + kc1); cpa16(bh+16, bhs0 + kc1 + 8);
            cpa16(bl, bls0 + kc1); cpa16(bl+16, bls0 + kc1 + 8);
            CPA_COMMIT;
        }

        // convert A chunk ic: smem fp32 -> bnrelu -> bf16 hi/lo tiles
        {
            int kc0 = ic*KC;
            const float* af = (const float*)(dsm + SM_AF(buf)) + lr*AFSTRIDE + cg;
            float v[16];
            *(float4*)(v)    = *(const float4*)(af);
            *(float4*)(v+4)  = *(const float4*)(af+4);
            *(float4*)(v+8)  = *(const float4*)(af+8);
            *(float4*)(v+12) = *(const float4*)(af+12);
            unsigned hh[8], ll[8];
#pragma unroll
            for (int p=0;p<8;p++){
                float a0 = v[p*2], a1 = v[p*2+1];
                if (BNRELU){
                    int c = kc0 + cg + p*2;
                    a0 = fmaxf(0.f, fmaf(a0, bnp[c],   bnp[256+c]));
                    a1 = fmaxf(0.f, fmaf(a1, bnp[c+1], bnp[257+c]));
                }
                __nv_bfloat16 h0 = __float2bfloat16_rn(a0);
                __nv_bfloat16 h1 = __float2bfloat16_rn(a1);
                __nv_bfloat16 l0 = __float2bfloat16_rn(a0 - __bfloat162float(h0));
                __nv_bfloat16 l1 = __float2bfloat16_rn(a1 - __bfloat162float(h1));
                hh[p] = (unsigned)__bfloat16_as_ushort(h0) | ((unsigned)__bfloat16_as_ushort(h1)<<16);
                ll[p] = (unsigned)__bfloat16_as_ushort(l0) | ((unsigned)__bfloat16_as_ushort(l1)<<16);
            }
            unsigned short (*AsH)[RSTRIDE] = (unsigned short(*)[RSTRIDE])(dsm + SM_ASH);
            unsigned short (*AsL)[RSTRIDE] = (unsigned short(*)[RSTRIDE])(dsm + SM_ASL);
            *(uint4*)&AsH[lr][cg]   = make_uint4(hh[0],hh[1],hh[2],hh[3]);
            *(uint4*)&AsH[lr][cg+8] = make_uint4(hh[4],hh[5],hh[6],hh[7]);
            *(uint4*)&AsL[lr][cg]   = make_uint4(ll[0],ll[1],ll[2],ll[3]);
            *(uint4*)&AsL[lr][cg+8] = make_uint4(ll[4],ll[5],ll[6],ll[7]);
        }
        __syncthreads();

        unsigned aASH = sb + SM_ASH, aASL = sb + SM_ASL;
        unsigned aBH  = sb + SM_BH(buf), aBL = sb + SM_BL(buf);
#pragma unroll
        for (int p=0;p<3;p++){
            unsigned Abase = (p==2)? aASL : aASH;
            unsigned Bbase = (p==1)? aBL  : aBH;
#pragma unroll
            for (int ks=0; ks<KC; ks+=16){
                unsigned af[2][4];
#pragma unroll
                for (int mt=0;mt<2;mt++)
                    ldmx4(af[mt], Abase + aoffA + (unsigned)((mt*16*RSTRIDE + ks)*2));
#pragma unroll
                for (int ntp=0;ntp<4;ntp++){
                    unsigned bb[4];
                    ldmx4(bb, Bbase + aoffB + (unsigned)((ntp*16*RSTRIDE + ks)*2));
                    mma_bf16(acc[0][2*ntp],   af[0], bb);
                    mma_bf16(acc[1][2*ntp],   af[1], bb);
                    mma_bf16(acc[0][2*ntp+1], af[0], bb+2);
                    mma_bf16(acc[1][2*ntp+1], af[1], bb+2);
                }
            }
        }
    }
}

// ---------------- GEMM (qkv / gamma1): store C, optional BN+fused stats ----------------
template<bool BNRELU, bool STATS>
__global__ __launch_bounds__(256, 2) void gemm_mma_kernel(
    const float* __restrict__ A,
    const __nv_bfloat16* __restrict__ Bh, const __nv_bfloat16* __restrict__ Bl,
    const float* __restrict__ bias, const float* __restrict__ bnp,
    float* __restrict__ C, float* __restrict__ psum, float* __restrict__ psq)
{
    extern __shared__ __align__(128) char dsm[];

    int tid = threadIdx.x, wid = tid >> 5, lane = tid & 31;
    int g = lane >> 2, t = lane & 3;
    int wm = wid & 3, wn = wid >> 2;
    const size_t rowbase = (size_t)blockIdx.x * 128;
    const int ncb = blockIdx.y * 128;

    float acc[2][8][4];
#pragma unroll
    for (int mt=0;mt<2;mt++)
#pragma unroll
        for (int nt=0;nt<8;nt++)
#pragma unroll
            for (int i=0;i<4;i++) acc[mt][nt][i]=0.f;

    gemm_mainloop<BNRELU>(A, Bh, Bl, bnp, dsm, rowbase, ncb, tid, wm, wn, acc);

#pragma unroll
    for (int nt=0;nt<8;nt++){
        int col = ncb + wn*64 + nt*8 + 2*t;
        float b0 = bias[col], b1 = bias[col+1];
#pragma unroll
        for (int mt=0;mt<2;mt++){
            acc[mt][nt][0]+=b0; acc[mt][nt][1]+=b1;
            acc[mt][nt][2]+=b0; acc[mt][nt][3]+=b1;
        }
    }
#pragma unroll
    for (int nt=0;nt<8;nt++){
        int col = ncb + wn*64 + nt*8 + 2*t;
#pragma unroll
        for (int mt=0;mt<2;mt++){
            size_t row = rowbase + wm*32 + mt*16 + g;
            *(float2*)&C[row*256 + col]     = make_float2(acc[mt][nt][0], acc[mt][nt][1]);
            *(float2*)&C[(row+8)*256 + col] = make_float2(acc[mt][nt][2], acc[mt][nt][3]);
        }
    }

    if (STATS){
        __syncthreads();
        float* sS = (float*)dsm;              // [4][128]
        float* sQ = sS + 512;
#pragma unroll
        for (int nt=0;nt<8;nt++){
            float s0=0.f,q0=0.f,s1=0.f,q1=0.f;
#pragma unroll
            for (int mt=0;mt<2;mt++){
                float v0=acc[mt][nt][0], v2=acc[mt][nt][2];
                float v1=acc[mt][nt][1], v3=acc[mt][nt][3];
                s0 += v0+v2;  q0 += v0*v0+v2*v2;
                s1 += v1+v3;  q1 += v1*v1+v3*v3;
            }
#pragma unroll
            for (int off=16; off>=4; off>>=1){
                s0 += __shfl_down_sync(0xffffffffu, s0, off);
                q0 += __shfl_down_sync(0xffffffffu, q0, off);
                s1 += __shfl_down_sync(0xffffffffu, s1, off);
                q1 += __shfl_down_sync(0xffffffffu, q1, off);
            }
            if (lane < 4){
                int c = wn*64 + nt*8 + 2*lane;
                sS[wm*128 + c]     = s0;  sS[wm*128 + c + 1] = s1;
                sQ[wm*128 + c]     = q0;  sQ[wm*128 + c + 1] = q1;
            }
        }
        __syncthreads();
        if (tid < 128){
            float s = sS[tid] + sS[128+tid] + sS[256+tid] + sS[384+tid];
            float q = sQ[tid] + sQ[128+tid] + sQ[256+tid] + sQ[384+tid];
            psum[blockIdx.x*256 + ncb + tid] = s;
            psq [blockIdx.x*256 + ncb + tid] = q;
        }
    }
}

// ---------------- fused gamma2 + softmax(K) + weighted output ----------------
#define VSTRIDE 132
__global__ __launch_bounds__(256, 2) void gemm_attn_kernel(
    const float* __restrict__ A,
    const __nv_bfloat16* __restrict__ Bh, const __nv_bfloat16* __restrict__ Bl,
    const float* __restrict__ bias, const float* __restrict__ bnp,
    const float* __restrict__ d2w, const float* __restrict__ d2b,
    float* __restrict__ out)
{
    extern __shared__ __align__(128) char dsm[];
    float* Vs = (float*)dsm;                     // reused after mainloop: 128 x VSTRIDE

    int tid = threadIdx.x, wid = tid >> 5, lane = tid & 31;
    int g = lane >> 2, t = lane & 3;
    int wm = wid & 3, wn = wid >> 2;
    const size_t rowbase = (size_t)blockIdx.x * 128;
    const int ncb = blockIdx.y * 128;

    float acc[2][8][4];
#pragma unroll
    for (int mt=0;mt<2;mt++)
#pragma unroll
        for (int nt=0;nt<8;nt++)
#pragma unroll
            for (int i=0;i<4;i++) acc[mt][nt][i]=0.f;

    gemm_mainloop<true>(A, Bh, Bl, bnp, dsm, rowbase, ncb, tid, wm, wn, acc);

    // bias -> logits
#pragma unroll
    for (int nt=0;nt<8;nt++){
        int col = ncb + wn*64 + nt*8 + 2*t;
        float b0 = bias[col], b1 = bias[col+1];
#pragma unroll
        for (int mt=0;mt<2;mt++){
            acc[mt][nt][0]+=b0; acc[mt][nt][1]+=b1;
            acc[mt][nt][2]+=b0; acc[mt][nt][3]+=b1;
        }
    }

    __syncthreads();   // tiles no longer needed; reuse as Vs

    // stage gathered v rows
    {
        int r = tid >> 1;
        int half = (tid & 1) * 64;
        size_t grow = rowbase + r;
        int gpt = (int)(grow >> 4);
        int b = gpt >> 12;
        int j = g_idx[grow];
        const float* vp = g_vf + ((size_t)(b*NP + j))*256 + ncb + half;
        float* dst = Vs + r*VSTRIDE + half;
#pragma unroll
        for (int i=0;i<16;i++)
            *(float4*)(dst + i*4) = *(const float4*)(vp + i*4);
    }

    // softmax over K — register + shfl only
#pragma unroll
    for (int mt=0;mt<2;mt++)
#pragma unroll
    for (int nt=0;nt<8;nt++){
        float a0=acc[mt][nt][0], a1=acc[mt][nt][1], a2=acc[mt][nt][2], a3=acc[mt][nt][3];
        float m0 = fmaxf(a0,a2), m1 = fmaxf(a1,a3);
#pragma unroll
        for (int mk=4; mk<=16; mk<<=1){
            m0 = fmaxf(m0, __shfl_xor_sync(0xffffffffu, m0, mk));
            m1 = fmaxf(m1, __shfl_xor_sync(0xffffffffu, m1, mk));
        }
        float e0=expf(a0-m0), e2=expf(a2-m0), e1=expf(a1-m1), e3=expf(a3-m1);
        float s0=e0+e2, s1=e1+e3;
#pragma unroll
        for (int mk=4; mk<=16; mk<<=1){
            s0 += __shfl_xor_sync(0xffffffffu, s0, mk);
            s1 += __shfl_xor_sync(0xffffffffu, s1, mk);
        }
        float i0=1.f/s0, i1=1.f/s1;
        acc[mt][nt][0]=e0*i0; acc[mt][nt][1]=e1*i1;
        acc[mt][nt][2]=e2*i0; acc[mt][nt][3]=e3*i1;
    }

    // u vectors for this thread's 2x2 k-rows
    float3 uv[2][2];
#pragma unroll
    for (int mt=0;mt<2;mt++)
#pragma unroll
    for (int kk=0;kk<2;kk++){
        size_t r = rowbase + wm*32 + mt*16 + g + kk*8;
        uv[mt][kk] = make_float3(g_u[r*3], g_u[r*3+1], g_u[r*3+2]);
    }

    __syncthreads();   // Vs ready

    // weighted output
#pragma unroll
    for (int nt=0;nt<8;nt++){
        int c0 = wn*64 + nt*8 + 2*t;
        int gc = ncb + c0;
        float w0a=d2w[gc],   w1a=d2w[256+gc],   w2a=d2w[512+gc],   ba=d2b[gc];
        float w0b=d2w[gc+1], w1b=d2w[257+gc],   w2b=d2w[513+gc],   bb=d2b[gc+1];
#pragma unroll
        for (int mt=0;mt<2;mt++){
            float o0=0.f, o1=0.f;
#pragma unroll
            for (int kk=0;kk<2;kk++){
                int r = wm*32 + mt*16 + g + kk*8;
                float2 v = *(const float2*)&Vs[r*VSTRIDE + c0];
                float3 u = uv[mt][kk];
                float pea = u.x*w0a + u.y*w1a + u.z*w2a + ba;
                float peb = u.x*w0b + u.y*w1b + u.z*w2b + bb;
                o0 += acc[mt][nt][kk*2+0] * (v.x + pea);
                o1 += acc[mt][nt][kk*2+1] * (v.y + peb);
            }
#pragma unroll
            for (int mk=4; mk<=16; mk<<=1){
                o0 += __shfl_xor_sync(0xffffffffu, o0, mk);
                o1 += __shfl_xor_sync(0xffffffffu, o1, mk);
            }
            if (g == 0){
                size_t pt = (rowbase >> 4) + 2*wm + mt;
                *(float2*)&out[pt*256 + gc] = make_float2(o0, o1);
            }
        }
    }
}

// ---------------- finalize per-channel BN over 256 channels ----------------
__global__ __launch_bounds__(256) void bnfin_kernel(const float* __restrict__ psum,
                                                    const float* __restrict__ psq, int P,
                                                    const float* __restrict__ g,
                                                    const float* __restrict__ beta,
                                                    float* __restrict__ outp)
{
    int c = threadIdx.x;
    double s=0.0,q=0.0;
    for (int i=0;i<P;i++){ s+=psum[i*NC+c]; q+=psq[i*NC+c]; }
    double m = s/(double)NROWS;
    double v = q/(double)NROWS - m*m;
    double sc = (double)g[c] / sqrt(v+1e-5);
    outp[c]    = (float)sc;
    outp[NC+c] = (float)((double)beta[c] - m*sc);
}

// ---------------- h producer ----------------
__global__ __launch_bounds__(256) void hprod_kernel(
    const float* __restrict__ xyz, const float* __restrict__ d1w, const float* __restrict__ d1b,
    const float* __restrict__ d2w, const float* __restrict__ d2b)
{
    __shared__ float su[NK*3];
    __shared__ int   sj[NK];
    int c = threadIdx.x;
    float d2c0 = d2w[c], d2c1 = d2w[256+c], d2c2 = d2w[512+c], d2bc = d2b[c];
    float s=0.f, q=0.f;
    for (int pp=0; pp<32; pp++){
        int pt = blockIdx.x*32 + pp;
        int b  = pt >> 12;
        if (c < NK){
            int k = c;
            int j = g_idx[pt*NK+k];
            sj[k]=j;
            float r0 = xyz[pt*3+0]-xyz[(b*NP+j)*3+0];
            float r1 = xyz[pt*3+1]-xyz[(b*NP+j)*3+1];
            float r2 = xyz[pt*3+2]-xyz[(b*NP+j)*3+2];
#pragma unroll
            for (int d=0;d<3;d++){
                float t  = r0*d1w[d] + r1*d1w[3+d] + r2*d1w[6+d] + d1b[d];
                float uu = fmaxf(0.f, fmaf(t, g_bnd[d], g_bnd[3+d]));
                su[k*3+d]=uu;
                g_u[(pt*NK+k)*3+d]=uu;
            }
        }
        __syncthreads();
        float qv = g_q[pt*NC + c];
#pragma unroll
        for (int k=0;k<NK;k++){
            int j = sj[k];
            float kv = g_kf[(b*NP+j)*NC + c];
            float pe = su[k*3]*d2c0 + su[k*3+1]*d2c1 + su[k*3+2]*d2c2 + d2bc;
            float h = qv - kv + pe;
            g_h[(size_t)(pt*NK+k)*NC + c] = h;
            s += h; q += h*h;
        }
        __syncthreads();
    }
    g_ps1[blockIdx.x*NC+c]=s;
    g_pq1[blockIdx.x*NC+c]=q;
}

// ---------------- host launcher ----------------
extern "C" void kernel_launch(void* const* d_in, const int* in_sizes, int n_in,
                              void* d_out, int out_size)
{
    const float* xyz  = (const float*)d_in[0];
    const float* feat = (const float*)d_in[1];
    const float* wq   = (const float*)d_in[2];  const float* bq  = (const float*)d_in[3];
    const float* wk   = (const float*)d_in[4];  const float* bk  = (const float*)d_in[5];
    const float* wv   = (const float*)d_in[6];  const float* bv  = (const float*)d_in[7];
    const float* d1w  = (const float*)d_in[8];  const float* d1b = (const float*)d_in[9];
    const float* bndg = (const float*)d_in[10]; const float* bndb= (const float*)d_in[11];
    const float* d2w  = (const float*)d_in[12]; const float* d2b = (const float*)d_in[13];
    const float* g1g  = (const float*)d_in[14]; const float* g1bt= (const float*)d_in[15];
    const float* g1w  = (const float*)d_in[16]; const float* g1b = (const float*)d_in[17];
    const float* g2g  = (const float*)d_in[18]; const float* g2bt= (const float*)d_in[19];
    const float* g2w  = (const float*)d_in[20]; const float* g2b = (const float*)d_in[21];
    float* out = (float*)d_out;

    float *p_q,*p_kf,*p_vf,*p_h,*p_h2,*p_bn1,*p_bn2,*p_ps1,*p_pq1,*p_ps2,*p_pq2;
    __nv_bfloat16 *p_bh1,*p_bl1,*p_bh2,*p_bl2,*p_bhq,*p_blq,*p_bhk,*p_blk,*p_bhv,*p_blv;
    cudaGetSymbolAddress((void**)&p_q,  g_q);
    cudaGetSymbolAddress((void**)&p_kf, g_kf);
    cudaGetSymbolAddress((void**)&p_vf, g_vf);
    cudaGetSymbolAddress((void**)&p_h,  g_h);
    cudaGetSymbolAddress((void**)&p_h2, g_h2);
    cudaGetSymbolAddress((void**)&p_bn1,g_bn1);
    cudaGetSymbolAddress((void**)&p_bn2,g_bn2);
    cudaGetSymbolAddress((void**)&p_ps1,g_ps1);
    cudaGetSymbolAddress((void**)&p_pq1,g_pq1);
    cudaGetSymbolAddress((void**)&p_ps2,g_ps2);
    cudaGetSymbolAddress((void**)&p_pq2,g_pq2);
    cudaGetSymbolAddress((void**)&p_bh1,g_bh1);
    cudaGetSymbolAddress((void**)&p_bl1,g_bl1);
    cudaGetSymbolAddress((void**)&p_bh2,g_bh2);
    cudaGetSymbolAddress((void**)&p_bl2,g_bl2);
    cudaGetSymbolAddress((void**)&p_bhq,g_bhq);
    cudaGetSymbolAddress((void**)&p_blq,g_blq);
    cudaGetSymbolAddress((void**)&p_bhk,g_bhk);
    cudaGetSymbolAddress((void**)&p_blk,g_blk);
    cudaGetSymbolAddress((void**)&p_bhv,g_bhv);
    cudaGetSymbolAddress((void**)&p_blv,g_blv);

    cudaFuncSetAttribute(gemm_mma_kernel<false,false>,
                         cudaFuncAttributeMaxDynamicSharedMemorySize, SM_TOTAL);
    cudaFuncSetAttribute(gemm_mma_kernel<true,true>,
                         cudaFuncAttributeMaxDynamicSharedMemorySize, SM_TOTAL);
    cudaFuncSetAttribute(gemm_attn_kernel,
                         cudaFuncAttributeMaxDynamicSharedMemorySize, SM_TOTAL);

    // Launch order keeps gemm_q at slot #4 (ncu capture).
    bprep5_kernel<<<dim3(NC,5),NC>>>(g1w, g2w, wq, wk, wv);
    knn_kernel<<<dim3(NP/16, NB), 512>>>(xyz);
    dstat_kernel<<<512,256>>>(xyz, d1w, d1b);
    gemm_mma_kernel<false,false><<<dim3(NPTS/128,2),256,SM_TOTAL>>>(feat, p_bhq, p_blq, bq, nullptr, p_q,  nullptr, nullptr);
    gemm_mma_kernel<false,false><<<dim3(NPTS/128,2),256,SM_TOTAL>>>(feat, p_bhk, p_blk, bk, nullptr, p_kf, nullptr, nullptr);
    gemm_mma_kernel<false,false><<<dim3(NPTS/128,2),256,SM_TOTAL>>>(feat, p_bhv, p_blv, bv, nullptr, p_vf, nullptr, nullptr);
    dfin_kernel<<<1,32>>>(bndg, bndb);
    hprod_kernel<<<512,256>>>(xyz, d1w, d1b, d2w, d2b);
    bnfin_kernel<<<1,256>>>(p_ps1, p_pq1, 512, g1g, g1bt, p_bn1);
    gemm_mma_kernel<true,true><<<dim3(NROWS/128,2),256,SM_TOTAL>>>(p_h, p_bh1, p_bl1, g1b, p_bn1, p_h2, p_ps2, p_pq2);
    bnfin_kernel<<<1,256>>>(p_ps2, p_pq2, 2048, g2g, g2bt, p_bn2);
    gemm_attn_kernel<<<dim3(NROWS/128,2),256,SM_TOTAL>>>(
        p_h2, p_bh2, p_bl2, g2b, p_bn2, d2w, d2b, out);
}